// round 1
// baseline (speedup 1.0000x reference)
#include <cuda_runtime.h>
#include <math.h>

#define Bn 32768
#define Dn 256
#define KN 32
#define Hn 8
#define DKn 32
#define FFn 1024
#define FFN_ROWS 8

// Scratch: post-attention residual x = x_anc + attn_out @ W_o   ([B, D] fp32)
__device__ float g_x[Bn * Dn];

// ---------------------------------------------------------------------------
// Kernel A: per-anchor fused LN1 -> Q -> K/V GEMM -> softmax attention -> W_o
// One CTA per b. 256 threads; thread j owns output column j everywhere.
// Warp w == head w (32 lanes == 32 neighbors / 32 head dims).
// ---------------------------------------------------------------------------
__global__ __launch_bounds__(256) void attn_kernel(
    const float* __restrict__ x_anc, const float* __restrict__ x_nei,
    const float* __restrict__ Wq, const float* __restrict__ Wk,
    const float* __restrict__ Wv, const float* __restrict__ Wo,
    const float* __restrict__ ln1g, const float* __restrict__ ln1b)
{
    __shared__ float xs[KN * Dn];     // 32 KB neighbor tile
    __shared__ float lnS[Dn];
    __shared__ float outS[Dn];
    __shared__ float red[16];

    const int b = blockIdx.x;
    const int j = threadIdx.x;
    const int wid = j >> 5, lid = j & 31;

    // ---- LN1 over x_anc[b] ----
    float xa = x_anc[(size_t)b * Dn + j];
    float s = xa, s2 = xa * xa;
    #pragma unroll
    for (int o = 16; o; o >>= 1) {
        s  += __shfl_xor_sync(0xffffffffu, s,  o);
        s2 += __shfl_xor_sync(0xffffffffu, s2, o);
    }
    if (lid == 0) { red[wid] = s; red[8 + wid] = s2; }
    __syncthreads();
    float ts = 0.f, ts2 = 0.f;
    #pragma unroll
    for (int i = 0; i < 8; i++) { ts += red[i]; ts2 += red[8 + i]; }
    const float mu   = ts * (1.0f / Dn);
    const float var  = ts2 * (1.0f / Dn) - mu * mu;
    const float rstd = rsqrtf(var + 1e-5f);
    lnS[j] = (xa - mu) * rstd * ln1g[j] + ln1b[j];
    __syncthreads();

    // ---- Q_j = ln . Wq[:, j]  (kept in register; lane lid == head dim) ----
    float q = 0.f;
    for (int i = 0; i < Dn; i += 4) {
        float4 lv = *(const float4*)&lnS[i];
        q = fmaf(lv.x, Wq[(i + 0) * Dn + j],
            fmaf(lv.y, Wq[(i + 1) * Dn + j],
            fmaf(lv.z, Wq[(i + 2) * Dn + j],
            fmaf(lv.w, Wq[(i + 3) * Dn + j], q))));
    }

    // ---- stage x_nei[b] (32 x 256) into smem ----
    {
        const float4* src = (const float4*)(x_nei + (size_t)b * KN * Dn);
        float4* dst = (float4*)xs;
        #pragma unroll
        for (int t = 0; t < (KN * Dn / 4) / 256; t++)
            dst[j + t * 256] = src[j + t * 256];
    }
    __syncthreads();

    // ---- K = x_nei @ Wk : thread j accumulates column j for all 32 rows ----
    float acc[KN];
    #pragma unroll
    for (int k = 0; k < KN; k++) acc[k] = 0.f;
    for (int i = 0; i < Dn; i += 4) {
        const float w0 = Wk[(i + 0) * Dn + j];
        const float w1 = Wk[(i + 1) * Dn + j];
        const float w2 = Wk[(i + 2) * Dn + j];
        const float w3 = Wk[(i + 3) * Dn + j];
        #pragma unroll
        for (int k = 0; k < KN; k++) {
            float4 xv = *(const float4*)&xs[k * Dn + i];   // warp-broadcast LDS.128
            acc[k] = fmaf(xv.x, w0, fmaf(xv.y, w1, fmaf(xv.z, w2, fmaf(xv.w, w3, acc[k]))));
        }
    }

    // ---- scores via warp butterfly reductions (no smem K tile needed) ----
    // Warp wid == head; lane lid holds K[k][head, d=lid] in acc[k], q = Q[head, d=lid].
    float sc = 0.f;
    #pragma unroll
    for (int k = 0; k < KN; k++) {
        float p = q * acc[k];
        #pragma unroll
        for (int o = 16; o; o >>= 1) p += __shfl_xor_sync(0xffffffffu, p, o);
        if (k == lid) sc = p;              // lane lid keeps score for neighbor lid
    }
    sc *= 0.17677669529663687f;            // 1/sqrt(32)

    // ---- softmax over 32 neighbors (one per lane) ----
    float m = sc;
    #pragma unroll
    for (int o = 16; o; o >>= 1) m = fmaxf(m, __shfl_xor_sync(0xffffffffu, m, o));
    float e = expf(sc - m);
    float es = e;
    #pragma unroll
    for (int o = 16; o; o >>= 1) es += __shfl_xor_sync(0xffffffffu, es, o);
    const float attn = e / es;

    // ---- V = x_nei @ Wv (reuse accumulators) ----
    #pragma unroll
    for (int k = 0; k < KN; k++) acc[k] = 0.f;
    for (int i = 0; i < Dn; i += 4) {
        const float w0 = Wv[(i + 0) * Dn + j];
        const float w1 = Wv[(i + 1) * Dn + j];
        const float w2 = Wv[(i + 2) * Dn + j];
        const float w3 = Wv[(i + 3) * Dn + j];
        #pragma unroll
        for (int k = 0; k < KN; k++) {
            float4 xv = *(const float4*)&xs[k * Dn + i];
            acc[k] = fmaf(xv.x, w0, fmaf(xv.y, w1, fmaf(xv.z, w2, fmaf(xv.w, w3, acc[k]))));
        }
    }

    // ---- out_j = sum_k attn[k] * V[k][j]  (attn lives on lane k) ----
    float ov = 0.f;
    #pragma unroll
    for (int k = 0; k < KN; k++)
        ov = fmaf(__shfl_sync(0xffffffffu, attn, k), acc[k], ov);
    outS[j] = ov;
    __syncthreads();

    // ---- x = x_anc + out @ Wo ----
    float y = 0.f;
    for (int i = 0; i < Dn; i += 4) {
        float4 t4 = *(const float4*)&outS[i];
        y = fmaf(t4.x, Wo[(i + 0) * Dn + j],
            fmaf(t4.y, Wo[(i + 1) * Dn + j],
            fmaf(t4.z, Wo[(i + 2) * Dn + j],
            fmaf(t4.w, Wo[(i + 3) * Dn + j], y))));
    }
    g_x[(size_t)b * Dn + j] = xa + y;
}

// ---------------------------------------------------------------------------
// Kernel B: row-batched LN2 + FFN (GELU exact) + residual.
// 8 rows per CTA amortizes the 2 MB of ff1/ff2 weight reads.
// ---------------------------------------------------------------------------
__global__ __launch_bounds__(256) void ffn_kernel(
    const float* __restrict__ ln2g, const float* __restrict__ ln2b,
    const float* __restrict__ ff1w, const float* __restrict__ ff1b,
    const float* __restrict__ ff2w, const float* __restrict__ ff2b,
    float* __restrict__ out)
{
    __shared__ float ys[FFN_ROWS * Dn];    // raw residual rows (8 KB)
    __shared__ float hs[FFN_ROWS * Dn];    // LN2 rows          (8 KB)
    __shared__ float gS[FFN_ROWS * FFn];   // gelu activations  (32 KB)

    const int j = threadIdx.x;
    const int row0 = blockIdx.x * FFN_ROWS;

    // load 8 residual rows
    {
        const float4* src = (const float4*)(g_x + (size_t)row0 * Dn);
        float4* dst = (float4*)ys;
        dst[j]       = src[j];
        dst[j + 256] = src[j + 256];
    }
    __syncthreads();

    // LN2: warp r normalizes row r (8 warps == 8 rows)
    const int r = j >> 5, l = j & 31;
    float v[8];
    float s = 0.f, s2 = 0.f;
    #pragma unroll
    for (int t = 0; t < 8; t++) {
        v[t] = ys[r * Dn + l * 8 + t];
        s += v[t]; s2 += v[t] * v[t];
    }
    #pragma unroll
    for (int o = 16; o; o >>= 1) {
        s  += __shfl_xor_sync(0xffffffffu, s,  o);
        s2 += __shfl_xor_sync(0xffffffffu, s2, o);
    }
    const float mu   = s * (1.0f / Dn);
    const float var  = s2 * (1.0f / Dn) - mu * mu;
    const float rstd = rsqrtf(var + 1e-5f);
    #pragma unroll
    for (int t = 0; t < 8; t++) {
        const int c = l * 8 + t;
        hs[r * Dn + c] = (v[t] - mu) * rstd * ln2g[c] + ln2b[c];
    }
    __syncthreads();

    // ff1: thread j computes cols {j, j+256, j+512, j+768} for all 8 rows
    float acc[32];
    #pragma unroll
    for (int t = 0; t < 32; t++) acc[t] = 0.f;
    for (int i = 0; i < Dn; i += 4) {
        #pragma unroll
        for (int cc = 0; cc < 4; cc++) {
            const int c = j + cc * Dn;
            const float w0 = ff1w[(i + 0) * FFn + c];
            const float w1 = ff1w[(i + 1) * FFn + c];
            const float w2 = ff1w[(i + 2) * FFn + c];
            const float w3 = ff1w[(i + 3) * FFn + c];
            #pragma unroll
            for (int rr = 0; rr < FFN_ROWS; rr++) {
                float4 hv = *(const float4*)&hs[rr * Dn + i];
                acc[rr * 4 + cc] = fmaf(hv.x, w0, fmaf(hv.y, w1,
                                   fmaf(hv.z, w2, fmaf(hv.w, w3, acc[rr * 4 + cc]))));
            }
        }
    }
    // bias + exact GELU
    #pragma unroll
    for (int cc = 0; cc < 4; cc++) {
        const int c = j + cc * Dn;
        const float bb = ff1b[c];
        #pragma unroll
        for (int rr = 0; rr < FFN_ROWS; rr++) {
            const float u = acc[rr * 4 + cc] + bb;
            gS[rr * FFn + c] = 0.5f * u * (1.0f + erff(u * 0.70710678118654752f));
        }
    }
    __syncthreads();

    // ff2: thread j computes output col j for all 8 rows
    float z[FFN_ROWS];
    #pragma unroll
    for (int rr = 0; rr < FFN_ROWS; rr++) z[rr] = 0.f;
    for (int i = 0; i < FFn; i += 4) {
        const float w0 = ff2w[(i + 0) * Dn + j];
        const float w1 = ff2w[(i + 1) * Dn + j];
        const float w2 = ff2w[(i + 2) * Dn + j];
        const float w3 = ff2w[(i + 3) * Dn + j];
        #pragma unroll
        for (int rr = 0; rr < FFN_ROWS; rr++) {
            float4 gv = *(const float4*)&gS[rr * FFn + i];
            z[rr] = fmaf(gv.x, w0, fmaf(gv.y, w1, fmaf(gv.z, w2, fmaf(gv.w, w3, z[rr]))));
        }
    }
    const float fb = ff2b[j];
    #pragma unroll
    for (int rr = 0; rr < FFN_ROWS; rr++)
        out[(size_t)(row0 + rr) * Dn + j] = ys[rr * Dn + j] + z[rr] + fb;
}

extern "C" void kernel_launch(void* const* d_in, const int* in_sizes, int n_in,
                              void* d_out, int out_size)
{
    const float* x_anc = (const float*)d_in[0];
    const float* x_nei = (const float*)d_in[1];
    const float* Wq    = (const float*)d_in[2];
    const float* Wk    = (const float*)d_in[3];
    const float* Wv    = (const float*)d_in[4];
    const float* Wo    = (const float*)d_in[5];
    const float* ln1g  = (const float*)d_in[6];
    const float* ln1b  = (const float*)d_in[7];
    const float* ln2g  = (const float*)d_in[8];
    const float* ln2b  = (const float*)d_in[9];
    const float* ff1w  = (const float*)d_in[10];
    const float* ff1b  = (const float*)d_in[11];
    const float* ff2w  = (const float*)d_in[12];
    const float* ff2b  = (const float*)d_in[13];
    float* out = (float*)d_out;

    attn_kernel<<<Bn, 256>>>(x_anc, x_nei, Wq, Wk, Wv, Wo, ln1g, ln1b);
    ffn_kernel<<<Bn / FFN_ROWS, 256>>>(ln2g, ln2b, ff1w, ff1b, ff2w, ff2b, out);
}

// round 3
// speedup vs baseline: 3.2526x; 3.2526x over previous
#include <cuda_runtime.h>
#include <math.h>
#include <stdint.h>

#define Bn 32768
#define Dn 256
#define KN 32
#define FFn 1024
#define FFN_ROWS 8
#define APB 8                 // anchors per CTA

// residual after attention
__device__ float g_x[Bn * Dn];

// ---- dynamic smem layout (floats) ----
#define SM_Q 0                // [8][256]   Q
#define SM_C 2048             // [8*8][256] c[a][h][d']
#define SM_U 18432            // [8*8][256] u[a][h][d']  (alias: LN1 rows)
#define SM_S 34816            // [8][33]    scores
#define SM_A 35080            // [8][33]    attn
#define SM_O 35344            // [8][256]   attn out rows (alias: raw x_anc rows)
#define SM_TOT 37392
#define SMEM_BYTES (SM_TOT * 4)

// ---------------------------------------------------------------------------
// Fused attention: LN1 -> Q -> c=Wk.Q -> scores -> softmax -> u=attn.x ->
// out=u.Wv -> x = x_anc + out.Wo.    8 anchors per CTA, 256 threads.
// ---------------------------------------------------------------------------
__global__ __launch_bounds__(256, 1) void attn3(
    const float* __restrict__ x_anc, const float* __restrict__ x_nei,
    const float* __restrict__ Wq, const float* __restrict__ Wk,
    const float* __restrict__ Wv, const float* __restrict__ Wo,
    const float* __restrict__ g1, const float* __restrict__ b1)
{
    extern __shared__ float sf[];
    float* qS = sf + SM_Q;
    float* cS = sf + SM_C;
    float* uS = sf + SM_U;
    float* sS = sf + SM_S;
    float* aS = sf + SM_A;
    float* oS = sf + SM_O;
    float* hS = uS;            // LN1 rows live in uS before u-phase

    const int tid = threadIdx.x, wid = tid >> 5, lane = tid & 31;
    const int b0 = blockIdx.x * APB;

    // ---- load 8 anchor rows into oS ----
    {
        const float4* src = (const float4*)(x_anc + (size_t)b0 * Dn);
        float4* dst = (float4*)oS;
        dst[tid] = src[tid];
        dst[tid + 256] = src[tid + 256];
    }
    __syncthreads();

    // ---- LN1: warp r normalizes row r ----
    {
        float v[8], s = 0.f, s2 = 0.f;
        #pragma unroll
        for (int t = 0; t < 8; t++) {
            v[t] = oS[wid * Dn + lane * 8 + t];
            s += v[t]; s2 += v[t] * v[t];
        }
        #pragma unroll
        for (int o = 16; o; o >>= 1) {
            s  += __shfl_xor_sync(0xffffffffu, s,  o);
            s2 += __shfl_xor_sync(0xffffffffu, s2, o);
        }
        const float mu   = s * (1.0f / Dn);
        const float var  = s2 * (1.0f / Dn) - mu * mu;
        const float rstd = rsqrtf(var + 1e-5f);
        #pragma unroll
        for (int t = 0; t < 8; t++) {
            const int c = lane * 8 + t;
            hS[wid * Dn + c] = (v[t] - mu) * rstd * g1[c] + b1[c];
        }
    }
    __syncthreads();

    // ---- Q = LN1 @ Wq : thread j owns col j, 8 anchors ----
    {
        float qa[8];
        #pragma unroll
        for (int a = 0; a < 8; a++) qa[a] = 0.f;
        for (int i = 0; i < Dn; i += 4) {
            const float w0 = Wq[(i + 0) * Dn + tid];
            const float w1 = Wq[(i + 1) * Dn + tid];
            const float w2 = Wq[(i + 2) * Dn + tid];
            const float w3 = Wq[(i + 3) * Dn + tid];
            #pragma unroll
            for (int a = 0; a < 8; a++) {
                float4 h4 = *(const float4*)&hS[a * Dn + i];
                qa[a] = fmaf(h4.x, w0, fmaf(h4.y, w1, fmaf(h4.z, w2, fmaf(h4.w, w3, qa[a]))));
            }
        }
        #pragma unroll
        for (int a = 0; a < 8; a++) qS[a * Dn + tid] = qa[a];
    }
    __syncthreads();

    // ---- c[a][h][j] = sum_d Wk[j][h*32+d] * Q[a][h*32+d]  (thread j = row j) ----
    {
        #pragma unroll
        for (int h = 0; h < 8; h++) {
            float4 wk[8];
            #pragma unroll
            for (int t = 0; t < 8; t++)
                wk[t] = *(const float4*)&Wk[tid * Dn + h * 32 + t * 4];
            #pragma unroll
            for (int a = 0; a < 8; a++) {
                float acc = 0.f;
                #pragma unroll
                for (int t = 0; t < 8; t++) {
                    float4 q4 = *(const float4*)&qS[a * Dn + h * 32 + t * 4];
                    acc = fmaf(wk[t].x, q4.x, fmaf(wk[t].y, q4.y,
                          fmaf(wk[t].z, q4.z, fmaf(wk[t].w, q4.w, acc))));
                }
                cS[(a * 8 + h) * Dn + tid] = acc;
            }
        }
    }
    __syncthreads();

    // ---- per-anchor: scores -> softmax -> u ----
    const int kk = tid >> 3;          // neighbor index (0..31)
    const int ss = tid & 7;           // d' interleave slice
    for (int a = 0; a < APB; a++) {
        const float* xb = x_nei + (size_t)(b0 + a) * (KN * Dn);

        // scores: thread (kk,ss) covers d' = ss*4 + 32*i (+0..3), i=0..7
        float p[8];
        #pragma unroll
        for (int h = 0; h < 8; h++) p[h] = 0.f;
        #pragma unroll
        for (int i = 0; i < 8; i++) {
            float4 x4 = *(const float4*)&xb[kk * Dn + ss * 4 + i * 32];
            #pragma unroll
            for (int h = 0; h < 8; h++) {
                float4 c4 = *(const float4*)&cS[(a * 8 + h) * Dn + ss * 4 + i * 32];
                p[h] = fmaf(x4.x, c4.x, fmaf(x4.y, c4.y,
                       fmaf(x4.z, c4.z, fmaf(x4.w, c4.w, p[h]))));
            }
        }
        #pragma unroll
        for (int o = 1; o <= 4; o <<= 1) {
            #pragma unroll
            for (int h = 0; h < 8; h++)
                p[h] += __shfl_xor_sync(0xffffffffu, p[h], o);
        }
        sS[ss * 33 + kk] = p[ss];     // lane writes h = ss
        __syncthreads();

        // softmax: warp h = wid, lane = neighbor
        {
            float sc = sS[wid * 33 + lane] * 0.17677669529663687f;  // 1/sqrt(32)
            float m = sc;
            #pragma unroll
            for (int o = 16; o; o >>= 1)
                m = fmaxf(m, __shfl_xor_sync(0xffffffffu, m, o));
            float e = expf(sc - m), es = e;
            #pragma unroll
            for (int o = 16; o; o >>= 1)
                es += __shfl_xor_sync(0xffffffffu, es, o);
            aS[wid * 33 + lane] = e / es;
        }
        __syncthreads();

        // u[h][j] = sum_k attn[h][k] * x[k][j]    (thread j = column j)
        {
            float xr[32];
            #pragma unroll
            for (int k = 0; k < KN; k++) xr[k] = xb[k * Dn + tid];
            float u[8];
            #pragma unroll
            for (int h = 0; h < 8; h++) u[h] = 0.f;
            #pragma unroll
            for (int k = 0; k < KN; k++) {
                #pragma unroll
                for (int h = 0; h < 8; h++)
                    u[h] = fmaf(aS[h * 33 + k], xr[k], u[h]);
            }
            #pragma unroll
            for (int h = 0; h < 8; h++)
                uS[(a * 8 + h) * Dn + tid] = u[h];
        }
        __syncthreads();
    }

    // ---- out[a][j] = sum_d' u[a][h(j)][d'] * Wv[d'][j] ----
    {
        const int hj = tid >> 5;
        float ot[8];
        #pragma unroll
        for (int a = 0; a < 8; a++) ot[a] = 0.f;
        for (int d = 0; d < Dn; d += 4) {
            const float w0 = Wv[(d + 0) * Dn + tid];
            const float w1 = Wv[(d + 1) * Dn + tid];
            const float w2 = Wv[(d + 2) * Dn + tid];
            const float w3 = Wv[(d + 3) * Dn + tid];
            #pragma unroll
            for (int a = 0; a < 8; a++) {
                float4 u4 = *(const float4*)&uS[(a * 8 + hj) * Dn + d];
                ot[a] = fmaf(u4.x, w0, fmaf(u4.y, w1, fmaf(u4.z, w2, fmaf(u4.w, w3, ot[a]))));
            }
        }
        __syncthreads();                // protect oS (held raw x rows) until here
        #pragma unroll
        for (int a = 0; a < 8; a++) oS[a * Dn + tid] = ot[a];
    }
    __syncthreads();

    // ---- x = x_anc + out @ Wo ----
    {
        float y[8];
        #pragma unroll
        for (int a = 0; a < 8; a++) y[a] = 0.f;
        for (int i = 0; i < Dn; i += 4) {
            const float w0 = Wo[(i + 0) * Dn + tid];
            const float w1 = Wo[(i + 1) * Dn + tid];
            const float w2 = Wo[(i + 2) * Dn + tid];
            const float w3 = Wo[(i + 3) * Dn + tid];
            #pragma unroll
            for (int a = 0; a < 8; a++) {
                float4 o4 = *(const float4*)&oS[a * Dn + i];
                y[a] = fmaf(o4.x, w0, fmaf(o4.y, w1, fmaf(o4.z, w2, fmaf(o4.w, w3, y[a]))));
            }
        }
        #pragma unroll
        for (int a = 0; a < 8; a++) {
            const size_t idx = (size_t)(b0 + a) * Dn + tid;
            g_x[idx] = x_anc[idx] + y[a];
        }
    }
}

// ---------------------------------------------------------------------------
// FFN kernel: row-batched LN2 + GELU FFN + residual (unchanged from R1).
// ---------------------------------------------------------------------------
__global__ __launch_bounds__(256) void ffn_kernel(
    const float* __restrict__ ln2g, const float* __restrict__ ln2b,
    const float* __restrict__ ff1w, const float* __restrict__ ff1b,
    const float* __restrict__ ff2w, const float* __restrict__ ff2b,
    float* __restrict__ out)
{
    __shared__ float ys[FFN_ROWS * Dn];
    __shared__ float hs[FFN_ROWS * Dn];
    __shared__ float gS[FFN_ROWS * FFn];

    const int j = threadIdx.x;
    const int row0 = blockIdx.x * FFN_ROWS;

    {
        const float4* src = (const float4*)(g_x + (size_t)row0 * Dn);
        float4* dst = (float4*)ys;
        dst[j]       = src[j];
        dst[j + 256] = src[j + 256];
    }
    __syncthreads();

    const int r = j >> 5, l = j & 31;
    float v[8];
    float s = 0.f, s2 = 0.f;
    #pragma unroll
    for (int t = 0; t < 8; t++) {
        v[t] = ys[r * Dn + l * 8 + t];
        s += v[t]; s2 += v[t] * v[t];
    }
    #pragma unroll
    for (int o = 16; o; o >>= 1) {
        s  += __shfl_xor_sync(0xffffffffu, s,  o);
        s2 += __shfl_xor_sync(0xffffffffu, s2, o);
    }
    const float mu   = s * (1.0f / Dn);
    const float var  = s2 * (1.0f / Dn) - mu * mu;
    const float rstd = rsqrtf(var + 1e-5f);
    #pragma unroll
    for (int t = 0; t < 8; t++) {
        const int c = l * 8 + t;
        hs[r * Dn + c] = (v[t] - mu) * rstd * ln2g[c] + ln2b[c];
    }
    __syncthreads();

    float acc[32];
    #pragma unroll
    for (int t = 0; t < 32; t++) acc[t] = 0.f;
    for (int i = 0; i < Dn; i += 4) {
        #pragma unroll
        for (int cc = 0; cc < 4; cc++) {
            const int c = j + cc * Dn;
            const float w0 = ff1w[(i + 0) * FFn + c];
            const float w1 = ff1w[(i + 1) * FFn + c];
            const float w2 = ff1w[(i + 2) * FFn + c];
            const float w3 = ff1w[(i + 3) * FFn + c];
            #pragma unroll
            for (int rr = 0; rr < FFN_ROWS; rr++) {
                float4 hv = *(const float4*)&hs[rr * Dn + i];
                acc[rr * 4 + cc] = fmaf(hv.x, w0, fmaf(hv.y, w1,
                                   fmaf(hv.z, w2, fmaf(hv.w, w3, acc[rr * 4 + cc]))));
            }
        }
    }
    #pragma unroll
    for (int cc = 0; cc < 4; cc++) {
        const int c = j + cc * Dn;
        const float bb = ff1b[c];
        #pragma unroll
        for (int rr = 0; rr < FFN_ROWS; rr++) {
            const float u = acc[rr * 4 + cc] + bb;
            gS[rr * FFn + c] = 0.5f * u * (1.0f + erff(u * 0.70710678118654752f));
        }
    }
    __syncthreads();

    float z[FFN_ROWS];
    #pragma unroll
    for (int rr = 0; rr < FFN_ROWS; rr++) z[rr] = 0.f;
    for (int i = 0; i < FFn; i += 4) {
        const float w0 = ff2w[(i + 0) * Dn + j];
        const float w1 = ff2w[(i + 1) * Dn + j];
        const float w2 = ff2w[(i + 2) * Dn + j];
        const float w3 = ff2w[(i + 3) * Dn + j];
        #pragma unroll
        for (int rr = 0; rr < FFN_ROWS; rr++) {
            float4 gv = *(const float4*)&gS[rr * FFn + i];
            z[rr] = fmaf(gv.x, w0, fmaf(gv.y, w1, fmaf(gv.z, w2, fmaf(gv.w, w3, z[rr]))));
        }
    }
    const float fb = ff2b[j];
    #pragma unroll
    for (int rr = 0; rr < FFN_ROWS; rr++)
        out[(size_t)(row0 + rr) * Dn + j] = ys[rr * Dn + j] + z[rr] + fb;
}

extern "C" void kernel_launch(void* const* d_in, const int* in_sizes, int n_in,
                              void* d_out, int out_size)
{
    const float* x_anc = (const float*)d_in[0];
    const float* x_nei = (const float*)d_in[1];
    const float* Wq    = (const float*)d_in[2];
    const float* Wk    = (const float*)d_in[3];
    const float* Wv    = (const float*)d_in[4];
    const float* Wo    = (const float*)d_in[5];
    const float* ln1g  = (const float*)d_in[6];
    const float* ln1b  = (const float*)d_in[7];
    const float* ln2g  = (const float*)d_in[8];
    const float* ln2b  = (const float*)d_in[9];
    const float* ff1w  = (const float*)d_in[10];
    const float* ff1b  = (const float*)d_in[11];
    const float* ff2w  = (const float*)d_in[12];
    const float* ff2b  = (const float*)d_in[13];
    float* out = (float*)d_out;

    static bool attr_set = false;
    if (!attr_set) {
        cudaFuncSetAttribute(attn3, cudaFuncAttributeMaxDynamicSharedMemorySize, SMEM_BYTES);
        attr_set = true;
    }

    attn3<<<Bn / APB, 256, SMEM_BYTES>>>(x_anc, x_nei, Wq, Wk, Wv, Wo, ln1g, ln1b);
    ffn_kernel<<<Bn / FFN_ROWS, 256>>>(ln2g, ln2b, ff1w, ff1b, ff2w, ff2b, out);
}

// round 4
// speedup vs baseline: 3.4754x; 1.0685x over previous
#include <cuda_runtime.h>
#include <math.h>
#include <stdint.h>

#define Bn 32768
#define Dn 256
#define KN 32
#define FFn 1024
#define APB 8                 // anchors per CTA (attn)
#define FM 32                 // rows per CTA (ffn)

// residual after attention
__device__ float g_x[Bn * Dn];

// ---- attn smem layout (floats) ----
#define SM_Q 0                // [8][256]
#define SM_C 2048             // [64][256]
#define SM_U 18432            // [64][256] (alias: LN1 rows)
#define SM_S 34816            // [8][33]
#define SM_A 35080            // [8][33]
#define SM_O 35344            // [8][256] (alias: raw x_anc rows)
#define SM_X 37392            // [32][264] staged x_nei tile
#define SM_TOT 45840
#define ATTN_SMEM (SM_TOT * 4)

// ---- ffn smem layout (floats) ----
#define FS_Y 0                // [32][256] raw rows
#define FS_H 8192             // [32][260] LN2 rows (padded for frag LDS)
#define FS_ACT 16512          // [32][516] gelu acts, one half of FF (padded)
#define FFN_SMEM ((16512 + 32 * 516) * 4)

// -------------------- tf32 mma helpers --------------------
__device__ __forceinline__ uint32_t f2tf(float f) {
    uint32_t u;
    asm("cvt.rna.tf32.f32 %0, %1;" : "=r"(u) : "f"(f));
    return u;
}

__device__ __forceinline__ void mma8(float* c, const uint32_t* a, const uint32_t* b) {
    asm volatile(
        "mma.sync.aligned.m16n8k8.row.col.f32.tf32.tf32.f32 "
        "{%0,%1,%2,%3}, {%4,%5,%6,%7}, {%8,%9}, {%0,%1,%2,%3};"
        : "+f"(c[0]), "+f"(c[1]), "+f"(c[2]), "+f"(c[3])
        : "r"(a[0]), "r"(a[1]), "r"(a[2]), "r"(a[3]), "r"(b[0]), "r"(b[1]));
}

// ---------------------------------------------------------------------------
// Attention: LN1 -> Q -> c = Wk.Q -> scores -> softmax -> u = attn.x ->
// out = u.Wv -> x = x_anc + out.Wo.   8 anchors / CTA, 256 threads.
// x_nei tile staged in smem once per anchor (single gmem read).
// ---------------------------------------------------------------------------
__global__ __launch_bounds__(256, 1) void attn4(
    const float* __restrict__ x_anc, const float* __restrict__ x_nei,
    const float* __restrict__ Wq, const float* __restrict__ Wk,
    const float* __restrict__ Wv, const float* __restrict__ Wo,
    const float* __restrict__ g1, const float* __restrict__ b1)
{
    extern __shared__ float sf[];
    float* qS = sf + SM_Q;
    float* cS = sf + SM_C;
    float* uS = sf + SM_U;
    float* sS = sf + SM_S;
    float* aS = sf + SM_A;
    float* oS = sf + SM_O;
    float* xs = sf + SM_X;
    float* hS = uS;

    const int tid = threadIdx.x, wid = tid >> 5, lane = tid & 31;
    const int b0 = blockIdx.x * APB;

    // ---- load 8 anchor rows ----
    {
        const float4* src = (const float4*)(x_anc + (size_t)b0 * Dn);
        float4* dst = (float4*)oS;
        dst[tid] = src[tid];
        dst[tid + 256] = src[tid + 256];
    }
    __syncthreads();

    // ---- LN1: warp r -> row r ----
    {
        float v[8], s = 0.f, s2 = 0.f;
        #pragma unroll
        for (int t = 0; t < 8; t++) {
            v[t] = oS[wid * Dn + lane * 8 + t];
            s += v[t]; s2 += v[t] * v[t];
        }
        #pragma unroll
        for (int o = 16; o; o >>= 1) {
            s  += __shfl_xor_sync(0xffffffffu, s,  o);
            s2 += __shfl_xor_sync(0xffffffffu, s2, o);
        }
        const float mu   = s * (1.0f / Dn);
        const float var  = s2 * (1.0f / Dn) - mu * mu;
        const float rstd = rsqrtf(var + 1e-5f);
        #pragma unroll
        for (int t = 0; t < 8; t++) {
            const int c = lane * 8 + t;
            hS[wid * Dn + c] = (v[t] - mu) * rstd * g1[c] + b1[c];
        }
    }
    __syncthreads();

    // ---- Q = LN1 @ Wq ----
    {
        float qa[8];
        #pragma unroll
        for (int a = 0; a < 8; a++) qa[a] = 0.f;
        for (int i = 0; i < Dn; i += 4) {
            const float w0 = Wq[(i + 0) * Dn + tid];
            const float w1 = Wq[(i + 1) * Dn + tid];
            const float w2 = Wq[(i + 2) * Dn + tid];
            const float w3 = Wq[(i + 3) * Dn + tid];
            #pragma unroll
            for (int a = 0; a < 8; a++) {
                float4 h4 = *(const float4*)&hS[a * Dn + i];
                qa[a] = fmaf(h4.x, w0, fmaf(h4.y, w1, fmaf(h4.z, w2, fmaf(h4.w, w3, qa[a]))));
            }
        }
        #pragma unroll
        for (int a = 0; a < 8; a++) qS[a * Dn + tid] = qa[a];
    }
    __syncthreads();

    // ---- c[a][h][j] = sum_d Wk[j][h*32+d] * Q[a][h*32+d] ----
    {
        #pragma unroll
        for (int h = 0; h < 8; h++) {
            float4 wk[8];
            #pragma unroll
            for (int t = 0; t < 8; t++)
                wk[t] = *(const float4*)&Wk[tid * Dn + h * 32 + t * 4];
            #pragma unroll
            for (int a = 0; a < 8; a++) {
                float acc = 0.f;
                #pragma unroll
                for (int t = 0; t < 8; t++) {
                    float4 q4 = *(const float4*)&qS[a * Dn + h * 32 + t * 4];
                    acc = fmaf(wk[t].x, q4.x, fmaf(wk[t].y, q4.y,
                          fmaf(wk[t].z, q4.z, fmaf(wk[t].w, q4.w, acc))));
                }
                cS[(a * 8 + h) * Dn + tid] = acc;
            }
        }
    }
    __syncthreads();

    // ---- per-anchor: stage x -> scores -> softmax -> u ----
    const int kk = tid >> 3;
    const int ss = tid & 7;
    for (int a = 0; a < APB; a++) {
        const float* xb = x_nei + (size_t)(b0 + a) * (KN * Dn);

        // stage x tile (32 x 256, stride 264)
        {
            const float4* src = (const float4*)xb;
            #pragma unroll
            for (int it = 0; it < 8; it++) {
                int idx = tid + it * 256;
                int row = idx >> 6, c4 = idx & 63;
                *(float4*)&xs[row * 264 + c4 * 4] = src[idx];
            }
        }
        __syncthreads();

        // scores from smem
        float p[8];
        #pragma unroll
        for (int h = 0; h < 8; h++) p[h] = 0.f;
        #pragma unroll
        for (int i = 0; i < 8; i++) {
            float4 x4 = *(const float4*)&xs[kk * 264 + ss * 4 + i * 32];
            #pragma unroll
            for (int h = 0; h < 8; h++) {
                float4 c4 = *(const float4*)&cS[(a * 8 + h) * Dn + ss * 4 + i * 32];
                p[h] = fmaf(x4.x, c4.x, fmaf(x4.y, c4.y,
                       fmaf(x4.z, c4.z, fmaf(x4.w, c4.w, p[h]))));
            }
        }
        #pragma unroll
        for (int o = 1; o <= 4; o <<= 1) {
            #pragma unroll
            for (int h = 0; h < 8; h++)
                p[h] += __shfl_xor_sync(0xffffffffu, p[h], o);
        }
        sS[ss * 33 + kk] = p[ss];
        __syncthreads();

        // softmax: warp h, lane = neighbor
        {
            float sc = sS[wid * 33 + lane] * 0.17677669529663687f;
            float m = sc;
            #pragma unroll
            for (int o = 16; o; o >>= 1)
                m = fmaxf(m, __shfl_xor_sync(0xffffffffu, m, o));
            float e = expf(sc - m), es = e;
            #pragma unroll
            for (int o = 16; o; o >>= 1)
                es += __shfl_xor_sync(0xffffffffu, es, o);
            aS[wid * 33 + lane] = e / es;
        }
        __syncthreads();

        // u[h][j] = sum_k attn[h][k] * x[k][j]
        {
            float xr[32];
            #pragma unroll
            for (int k = 0; k < KN; k++) xr[k] = xs[k * 264 + tid];
            float u[8];
            #pragma unroll
            for (int h = 0; h < 8; h++) u[h] = 0.f;
            #pragma unroll
            for (int k = 0; k < KN; k++) {
                #pragma unroll
                for (int h = 0; h < 8; h++)
                    u[h] = fmaf(aS[h * 33 + k], xr[k], u[h]);
            }
            #pragma unroll
            for (int h = 0; h < 8; h++)
                uS[(a * 8 + h) * Dn + tid] = u[h];
        }
        __syncthreads();
    }

    // ---- out[a][j] = sum_d u[a][h(j)][d] * Wv[d][j] ----
    {
        const int hj = tid >> 5;
        float ot[8];
        #pragma unroll
        for (int a = 0; a < 8; a++) ot[a] = 0.f;
        for (int d = 0; d < Dn; d += 4) {
            const float w0 = Wv[(d + 0) * Dn + tid];
            const float w1 = Wv[(d + 1) * Dn + tid];
            const float w2 = Wv[(d + 2) * Dn + tid];
            const float w3 = Wv[(d + 3) * Dn + tid];
            #pragma unroll
            for (int a = 0; a < 8; a++) {
                float4 u4 = *(const float4*)&uS[(a * 8 + hj) * Dn + d];
                ot[a] = fmaf(u4.x, w0, fmaf(u4.y, w1, fmaf(u4.z, w2, fmaf(u4.w, w3, ot[a]))));
            }
        }
        __syncthreads();
        #pragma unroll
        for (int a = 0; a < 8; a++) oS[a * Dn + tid] = ot[a];
    }
    __syncthreads();

    // ---- x = x_anc + out @ Wo ----
    {
        float y[8];
        #pragma unroll
        for (int a = 0; a < 8; a++) y[a] = 0.f;
        for (int i = 0; i < Dn; i += 4) {
            const float w0 = Wo[(i + 0) * Dn + tid];
            const float w1 = Wo[(i + 1) * Dn + tid];
            const float w2 = Wo[(i + 2) * Dn + tid];
            const float w3 = Wo[(i + 3) * Dn + tid];
            #pragma unroll
            for (int a = 0; a < 8; a++) {
                float4 o4 = *(const float4*)&oS[a * Dn + i];
                y[a] = fmaf(o4.x, w0, fmaf(o4.y, w1, fmaf(o4.z, w2, fmaf(o4.w, w3, y[a]))));
            }
        }
        #pragma unroll
        for (int a = 0; a < 8; a++) {
            const size_t idx = (size_t)(b0 + a) * Dn + tid;
            g_x[idx] = x_anc[idx] + y[a];
        }
    }
}

// ---------------------------------------------------------------------------
// FFN via 3xTF32 mma.sync: LN2 -> ff1(+bias,gelu) -> ff2(+bias) -> residual.
// 32 rows / CTA, 256 threads (8 warps). FF dim processed in 2 halves of 512
// so the gelu-activation buffer fits smem.
// ---------------------------------------------------------------------------
__global__ __launch_bounds__(256, 1) void ffn_mma(
    const float* __restrict__ ln2g, const float* __restrict__ ln2b,
    const float* __restrict__ ff1w, const float* __restrict__ ff1b,
    const float* __restrict__ ff2w, const float* __restrict__ ff2b,
    float* __restrict__ out)
{
    extern __shared__ float sf2[];
    float* ys  = sf2 + FS_Y;     // [32][256]
    float* hS  = sf2 + FS_H;     // [32][260]
    float* act = sf2 + FS_ACT;   // [32][516]

    const int tid = threadIdx.x, wid = tid >> 5, lane = tid & 31;
    const int lg = lane >> 2, lc = lane & 3;     // frag row-group / k-col
    const int row0 = blockIdx.x * FM;

    // ---- load 32 residual rows ----
    {
        const float4* src = (const float4*)(g_x + (size_t)row0 * Dn);
        float4* dst = (float4*)ys;
        #pragma unroll
        for (int it = 0; it < 8; it++)
            dst[tid + it * 256] = src[tid + it * 256];
    }
    __syncthreads();

    // ---- LN2: warp handles 4 rows ----
    #pragma unroll
    for (int rr = 0; rr < 4; rr++) {
        const int row = wid * 4 + rr;
        float v[8], s = 0.f, s2 = 0.f;
        #pragma unroll
        for (int t = 0; t < 8; t++) {
            v[t] = ys[row * Dn + lane * 8 + t];
            s += v[t]; s2 += v[t] * v[t];
        }
        #pragma unroll
        for (int o = 16; o; o >>= 1) {
            s  += __shfl_xor_sync(0xffffffffu, s,  o);
            s2 += __shfl_xor_sync(0xffffffffu, s2, o);
        }
        const float mu   = s * (1.0f / Dn);
        const float var  = s2 * (1.0f / Dn) - mu * mu;
        const float rstd = rsqrtf(var + 1e-5f);
        #pragma unroll
        for (int t = 0; t < 8; t++) {
            const int c = lane * 8 + t;
            hS[row * 260 + c] = (v[t] - mu) * rstd * ln2g[c] + ln2b[c];
        }
    }
    __syncthreads();

    float acc2[2][4][4];
    #pragma unroll
    for (int mt = 0; mt < 2; mt++)
        #pragma unroll
        for (int nt = 0; nt < 4; nt++)
            #pragma unroll
            for (int e = 0; e < 4; e++) acc2[mt][nt][e] = 0.f;

    for (int half = 0; half < 2; half++) {
        // ---- ff1: C[32 x 512-half] = h @ ff1w[:, half] ----
        float acc[2][8][4];
        #pragma unroll
        for (int mt = 0; mt < 2; mt++)
            #pragma unroll
            for (int nt = 0; nt < 8; nt++)
                #pragma unroll
                for (int e = 0; e < 4; e++) acc[mt][nt][e] = 0.f;

        for (int ks = 0; ks < 32; ks++) {
            const int kb = ks * 8;
            uint32_t ahi[2][4], alo[2][4];
            #pragma unroll
            for (int mt = 0; mt < 2; mt++) {
                const int r0 = mt * 16 + lg;
                float fa[4];
                fa[0] = hS[r0 * 260 + kb + lc];
                fa[1] = hS[(r0 + 8) * 260 + kb + lc];
                fa[2] = hS[r0 * 260 + kb + lc + 4];
                fa[3] = hS[(r0 + 8) * 260 + kb + lc + 4];
                #pragma unroll
                for (int e = 0; e < 4; e++) {
                    ahi[mt][e] = f2tf(fa[e]);
                    alo[mt][e] = f2tf(fa[e] - __uint_as_float(ahi[mt][e]));
                }
            }
            #pragma unroll
            for (int nt = 0; nt < 8; nt++) {
                const int nb = half * 512 + wid * 64 + nt * 8;
                float fb0 = ff1w[(kb + lc) * FFn + nb + lg];
                float fb1 = ff1w[(kb + lc + 4) * FFn + nb + lg];
                uint32_t bhi[2], blo[2];
                bhi[0] = f2tf(fb0); blo[0] = f2tf(fb0 - __uint_as_float(bhi[0]));
                bhi[1] = f2tf(fb1); blo[1] = f2tf(fb1 - __uint_as_float(bhi[1]));
                #pragma unroll
                for (int mt = 0; mt < 2; mt++) {
                    mma8(acc[mt][nt], alo[mt], bhi);
                    mma8(acc[mt][nt], ahi[mt], blo);
                    mma8(acc[mt][nt], ahi[mt], bhi);
                }
            }
        }

        // ---- bias + gelu -> act smem ----
        #pragma unroll
        for (int mt = 0; mt < 2; mt++) {
            const int r0 = mt * 16 + lg;
            #pragma unroll
            for (int nt = 0; nt < 8; nt++) {
                const int lcol = wid * 64 + nt * 8 + lc * 2;
                const int gcol = half * 512 + lcol;
                #pragma unroll
                for (int e = 0; e < 2; e++) {
                    const float bb = ff1b[gcol + e];
                    float u0 = acc[mt][nt][e] + bb;
                    float u1 = acc[mt][nt][2 + e] + bb;
                    act[r0 * 516 + lcol + e] =
                        0.5f * u0 * (1.0f + erff(u0 * 0.70710678118654752f));
                    act[(r0 + 8) * 516 + lcol + e] =
                        0.5f * u1 * (1.0f + erff(u1 * 0.70710678118654752f));
                }
            }
        }
        __syncthreads();

        // ---- ff2 partial accumulation over this half's K=512 ----
        for (int ks = 0; ks < 64; ks++) {
            const int kb = ks * 8;
            uint32_t ahi[2][4], alo[2][4];
            #pragma unroll
            for (int mt = 0; mt < 2; mt++) {
                const int r0 = mt * 16 + lg;
                float fa[4];
                fa[0] = act[r0 * 516 + kb + lc];
                fa[1] = act[(r0 + 8) * 516 + kb + lc];
                fa[2] = act[r0 * 516 + kb + lc + 4];
                fa[3] = act[(r0 + 8) * 516 + kb + lc + 4];
                #pragma unroll
                for (int e = 0; e < 4; e++) {
                    ahi[mt][e] = f2tf(fa[e]);
                    alo[mt][e] = f2tf(fa[e] - __uint_as_float(ahi[mt][e]));
                }
            }
            #pragma unroll
            for (int nt = 0; nt < 4; nt++) {
                const int nb = wid * 32 + nt * 8;
                float fb0 = ff2w[(half * 512 + kb + lc) * Dn + nb + lg];
                float fb1 = ff2w[(half * 512 + kb + lc + 4) * Dn + nb + lg];
                uint32_t bhi[2], blo[2];
                bhi[0] = f2tf(fb0); blo[0] = f2tf(fb0 - __uint_as_float(bhi[0]));
                bhi[1] = f2tf(fb1); blo[1] = f2tf(fb1 - __uint_as_float(bhi[1]));
                #pragma unroll
                for (int mt = 0; mt < 2; mt++) {
                    mma8(acc2[mt][nt], alo[mt], bhi);
                    mma8(acc2[mt][nt], ahi[mt], blo);
                    mma8(acc2[mt][nt], ahi[mt], bhi);
                }
            }
        }
        __syncthreads();
    }

    // ---- epilogue: residual + ff2 bias ----
    #pragma unroll
    for (int mt = 0; mt < 2; mt++) {
        const int r0 = mt * 16 + lg;
        #pragma unroll
        for (int nt = 0; nt < 4; nt++) {
            const int col = wid * 32 + nt * 8 + lc * 2;
            const float b0 = ff2b[col], b1 = ff2b[col + 1];
            out[(size_t)(row0 + r0) * Dn + col]         = ys[r0 * Dn + col]           + acc2[mt][nt][0] + b0;
            out[(size_t)(row0 + r0) * Dn + col + 1]     = ys[r0 * Dn + col + 1]       + acc2[mt][nt][1] + b1;
            out[(size_t)(row0 + r0 + 8) * Dn + col]     = ys[(r0 + 8) * Dn + col]     + acc2[mt][nt][2] + b0;
            out[(size_t)(row0 + r0 + 8) * Dn + col + 1] = ys[(r0 + 8) * Dn + col + 1] + acc2[mt][nt][3] + b1;
        }
    }
}

extern "C" void kernel_launch(void* const* d_in, const int* in_sizes, int n_in,
                              void* d_out, int out_size)
{
    const float* x_anc = (const float*)d_in[0];
    const float* x_nei = (const float*)d_in[1];
    const float* Wq    = (const float*)d_in[2];
    const float* Wk    = (const float*)d_in[3];
    const float* Wv    = (const float*)d_in[4];
    const float* Wo    = (const float*)d_in[5];
    const float* ln1g  = (const float*)d_in[6];
    const float* ln1b  = (const float*)d_in[7];
    const float* ln2g  = (const float*)d_in[8];
    const float* ln2b  = (const float*)d_in[9];
    const float* ff1w  = (const float*)d_in[10];
    const float* ff1b  = (const float*)d_in[11];
    const float* ff2w  = (const float*)d_in[12];
    const float* ff2b  = (const float*)d_in[13];
    float* out = (float*)d_out;

    static bool attr_set = false;
    if (!attr_set) {
        cudaFuncSetAttribute(attn4,   cudaFuncAttributeMaxDynamicSharedMemorySize, ATTN_SMEM);
        cudaFuncSetAttribute(ffn_mma, cudaFuncAttributeMaxDynamicSharedMemorySize, FFN_SMEM);
        attr_set = true;
    }

    attn4<<<Bn / APB, 256, ATTN_SMEM>>>(x_anc, x_nei, Wq, Wk, Wv, Wo, ln1g, ln1b);
    ffn_mma<<<Bn / FM, 256, FFN_SMEM>>>(ln2g, ln2b, ff1w, ff1b, ff2w, ff2b, out);
}

// round 5
// speedup vs baseline: 4.0144x; 1.1551x over previous
#include <cuda_runtime.h>
#include <math.h>
#include <stdint.h>

#define Bn 32768
#define Dn 256
#define KN 32
#define FFn 1024

// residual after attention
__device__ float g_x[Bn * Dn];
// pre-split tf32 weights (hi/lo)
__device__ uint32_t g_w1hi[Dn * FFn], g_w1lo[Dn * FFn];
__device__ uint32_t g_w2hi[FFn * Dn], g_w2lo[FFn * Dn];

// ---- attn smem layout (floats) ----
#define SM_H 0                // [8][256]   LN1 rows
#define SM_Q 2048             // [8][256]
#define SM_C 4096             // [64][256]
#define SM_U 20480            // [64][264]
#define SM_S 37376            // [2][8*33]
#define SM_A 37904            // [2][8*33]
#define SM_O 38432            // [8][256]
#define ATTN_SMEM (40480 * 4)

// ---- ffn smem layout (floats) ----
#define FS_H 0                // [32][260] LN2 rows
#define FS_ACT 8320           // [32][516] gelu acts (one half of FF)
#define FFN_SMEM ((8320 + 32 * 516) * 4)

__device__ __forceinline__ uint32_t f2tf(float f) {
    uint32_t u;
    asm("cvt.rna.tf32.f32 %0, %1;" : "=r"(u) : "f"(f));
    return u;
}

__device__ __forceinline__ void mma8(float* c, const uint32_t* a, const uint32_t* b) {
    asm volatile(
        "mma.sync.aligned.m16n8k8.row.col.f32.tf32.tf32.f32 "
        "{%0,%1,%2,%3}, {%4,%5,%6,%7}, {%8,%9}, {%0,%1,%2,%3};"
        : "+f"(c[0]), "+f"(c[1]), "+f"(c[2]), "+f"(c[3])
        : "r"(a[0]), "r"(a[1]), "r"(a[2]), "r"(a[3]), "r"(b[0]), "r"(b[1]));
}

// ---------------------------------------------------------------------------
// setup: pre-split ff1w / ff2w into tf32 hi/lo (removes B-side cvts in ffn).
// ---------------------------------------------------------------------------
__global__ void split_w(const float* __restrict__ ff1w, const float* __restrict__ ff2w) {
    int idx = blockIdx.x * 256 + threadIdx.x;     // 262144 elements each
    float f1 = ff1w[idx];
    uint32_t h1 = f2tf(f1);
    g_w1hi[idx] = h1;
    g_w1lo[idx] = f2tf(f1 - __uint_as_float(h1));
    float f2 = ff2w[idx];
    uint32_t h2 = f2tf(f2);
    g_w2hi[idx] = h2;
    g_w2lo[idx] = f2tf(f2 - __uint_as_float(h2));
}

// ---------------------------------------------------------------------------
// Attention: LN1 -> Q -> c=Wk.Q -> scores -> softmax -> u=attn.x ->
// out=u.Wv -> x = x_anc + out.Wo.  8 anchors / CTA, 512 threads (16 warps).
// Thread-half owns anchors 0-3 / 4-7; anchor pairs processed concurrently.
// ---------------------------------------------------------------------------
__global__ __launch_bounds__(512, 1) void attn5(
    const float* __restrict__ x_anc, const float* __restrict__ x_nei,
    const float* __restrict__ Wq, const float* __restrict__ Wk,
    const float* __restrict__ Wv, const float* __restrict__ Wo,
    const float* __restrict__ g1, const float* __restrict__ b1)
{
    extern __shared__ float sf[];
    float* hS = sf + SM_H;
    float* qS = sf + SM_Q;
    float* cS = sf + SM_C;
    float* uS = sf + SM_U;
    float* sS = sf + SM_S;
    float* aS = sf + SM_A;
    float* oS = sf + SM_O;

    const int tid = threadIdx.x, wid = tid >> 5, lane = tid & 31;
    const int j2 = tid & 255;
    const int a0 = (tid >> 8) * 4;          // anchor block: 0..3 or 4..7
    const int b0 = blockIdx.x * 8;

    // ---- LN1: warps 0-7, one row each ----
    if (wid < 8) {
        const float* xr = x_anc + (size_t)(b0 + wid) * Dn;
        float4 v0 = *(const float4*)&xr[lane * 8];
        float4 v1 = *(const float4*)&xr[lane * 8 + 4];
        float v[8] = {v0.x, v0.y, v0.z, v0.w, v1.x, v1.y, v1.z, v1.w};
        float s = 0.f, s2 = 0.f;
        #pragma unroll
        for (int t = 0; t < 8; t++) { s += v[t]; s2 += v[t] * v[t]; }
        #pragma unroll
        for (int o = 16; o; o >>= 1) {
            s  += __shfl_xor_sync(0xffffffffu, s,  o);
            s2 += __shfl_xor_sync(0xffffffffu, s2, o);
        }
        const float mu   = s * (1.0f / Dn);
        const float var  = s2 * (1.0f / Dn) - mu * mu;
        const float rstd = rsqrtf(var + 1e-5f);
        #pragma unroll
        for (int t = 0; t < 8; t++) {
            const int c = lane * 8 + t;
            hS[wid * Dn + c] = (v[t] - mu) * rstd * g1[c] + b1[c];
        }
    }
    __syncthreads();

    // ---- Q = LN1 @ Wq : thread covers col j2 for its 4 anchors ----
    {
        float qa[4] = {0.f, 0.f, 0.f, 0.f};
        for (int i = 0; i < Dn; i += 4) {
            const float w0 = Wq[(i + 0) * Dn + j2];
            const float w1 = Wq[(i + 1) * Dn + j2];
            const float w2 = Wq[(i + 2) * Dn + j2];
            const float w3 = Wq[(i + 3) * Dn + j2];
            #pragma unroll
            for (int a = 0; a < 4; a++) {
                float4 h4 = *(const float4*)&hS[(a0 + a) * Dn + i];
                qa[a] = fmaf(h4.x, w0, fmaf(h4.y, w1, fmaf(h4.z, w2, fmaf(h4.w, w3, qa[a]))));
            }
        }
        #pragma unroll
        for (int a = 0; a < 4; a++) qS[(a0 + a) * Dn + j2] = qa[a];
    }
    __syncthreads();

    // ---- c[a][h][j2] = sum_d Wk[j2][h*32+d] * Q[a][h*32+d] ----
    {
        #pragma unroll
        for (int h = 0; h < 8; h++) {
            float4 wk[8];
            #pragma unroll
            for (int t = 0; t < 8; t++)
                wk[t] = *(const float4*)&Wk[j2 * Dn + h * 32 + t * 4];
            #pragma unroll
            for (int a = 0; a < 4; a++) {
                float acc = 0.f;
                #pragma unroll
                for (int t = 0; t < 8; t++) {
                    float4 q4 = *(const float4*)&qS[(a0 + a) * Dn + h * 32 + t * 4];
                    acc = fmaf(wk[t].x, q4.x, fmaf(wk[t].y, q4.y,
                          fmaf(wk[t].z, q4.z, fmaf(wk[t].w, q4.w, acc))));
                }
                cS[((a0 + a) * 8 + h) * Dn + j2] = acc;
            }
        }
    }
    __syncthreads();

    // ---- anchor pairs: warp-group g handles anchor 2p+g ----
    const int g = wid >> 3;
    const int wid2 = wid & 7;
    const int kk = j2 >> 3, ss = j2 & 7;
    for (int p = 0; p < 4; p++) {
        const int a = 2 * p + g;
        const float* xb = x_nei + (size_t)(b0 + a) * (KN * Dn);

        // scores
        float pr[8];
        #pragma unroll
        for (int h = 0; h < 8; h++) pr[h] = 0.f;
        #pragma unroll
        for (int i = 0; i < 8; i++) {
            float4 x4 = *(const float4*)&xb[kk * Dn + ss * 4 + i * 32];
            #pragma unroll
            for (int h = 0; h < 8; h++) {
                float4 c4 = *(const float4*)&cS[(a * 8 + h) * Dn + ss * 4 + i * 32];
                pr[h] = fmaf(x4.x, c4.x, fmaf(x4.y, c4.y,
                        fmaf(x4.z, c4.z, fmaf(x4.w, c4.w, pr[h]))));
            }
        }
        #pragma unroll
        for (int o = 1; o <= 4; o <<= 1) {
            #pragma unroll
            for (int h = 0; h < 8; h++)
                pr[h] += __shfl_xor_sync(0xffffffffu, pr[h], o);
        }
        sS[g * 264 + ss * 33 + kk] = pr[ss];
        __syncthreads();

        // softmax: warp (g, h=wid2), lane = neighbor
        {
            float sc = sS[g * 264 + wid2 * 33 + lane] * 0.17677669529663687f;
            float m = sc;
            #pragma unroll
            for (int o = 16; o; o >>= 1)
                m = fmaxf(m, __shfl_xor_sync(0xffffffffu, m, o));
            float e = expf(sc - m), es = e;
            #pragma unroll
            for (int o = 16; o; o >>= 1)
                es += __shfl_xor_sync(0xffffffffu, es, o);
            aS[g * 264 + wid2 * 33 + lane] = e / es;
        }
        __syncthreads();

        // u[h][j2] = sum_k attn[h][k] * x[k][j2]
        {
            float xr2[32];
            #pragma unroll
            for (int k = 0; k < KN; k++) xr2[k] = xb[k * Dn + j2];
            float u[8];
            #pragma unroll
            for (int h = 0; h < 8; h++) u[h] = 0.f;
            #pragma unroll
            for (int k = 0; k < KN; k++) {
                #pragma unroll
                for (int h = 0; h < 8; h++)
                    u[h] = fmaf(aS[g * 264 + h * 33 + k], xr2[k], u[h]);
            }
            #pragma unroll
            for (int h = 0; h < 8; h++)
                uS[(a * 8 + h) * 264 + j2] = u[h];
        }
        __syncthreads();
    }

    // ---- out[a][j2] = sum_d u[a][h(j2)][d] * Wv[d][j2] ----
    {
        const int hj = j2 >> 5;
        float ot[4] = {0.f, 0.f, 0.f, 0.f};
        for (int d = 0; d < Dn; d += 4) {
            const float w0 = Wv[(d + 0) * Dn + j2];
            const float w1 = Wv[(d + 1) * Dn + j2];
            const float w2 = Wv[(d + 2) * Dn + j2];
            const float w3 = Wv[(d + 3) * Dn + j2];
            #pragma unroll
            for (int a = 0; a < 4; a++) {
                float4 u4 = *(const float4*)&uS[((a0 + a) * 8 + hj) * 264 + d];
                ot[a] = fmaf(u4.x, w0, fmaf(u4.y, w1, fmaf(u4.z, w2, fmaf(u4.w, w3, ot[a]))));
            }
        }
        #pragma unroll
        for (int a = 0; a < 4; a++) oS[(a0 + a) * Dn + j2] = ot[a];
    }
    __syncthreads();

    // ---- x = x_anc + out @ Wo ----
    {
        float y[4] = {0.f, 0.f, 0.f, 0.f};
        for (int i = 0; i < Dn; i += 4) {
            const float w0 = Wo[(i + 0) * Dn + j2];
            const float w1 = Wo[(i + 1) * Dn + j2];
            const float w2 = Wo[(i + 2) * Dn + j2];
            const float w3 = Wo[(i + 3) * Dn + j2];
            #pragma unroll
            for (int a = 0; a < 4; a++) {
                float4 o4 = *(const float4*)&oS[(a0 + a) * Dn + i];
                y[a] = fmaf(o4.x, w0, fmaf(o4.y, w1, fmaf(o4.z, w2, fmaf(o4.w, w3, y[a]))));
            }
        }
        #pragma unroll
        for (int a = 0; a < 4; a++) {
            const size_t idx = (size_t)(b0 + a0 + a) * Dn + j2;
            g_x[idx] = x_anc[idx] + y[a];
        }
    }
}

// ---------------------------------------------------------------------------
// FFN via 3xTF32 mma.sync, pre-split weights. 32 rows / CTA, 512 threads.
// ---------------------------------------------------------------------------
__global__ __launch_bounds__(512, 1) void ffn_mma2(
    const float* __restrict__ ln2g, const float* __restrict__ ln2b,
    const float* __restrict__ ff1b, const float* __restrict__ ff2b,
    float* __restrict__ out)
{
    extern __shared__ float sf2[];
    float* hS  = sf2 + FS_H;     // [32][260]
    float* act = sf2 + FS_ACT;   // [32][516]

    const int tid = threadIdx.x, wid = tid >> 5, lane = tid & 31;
    const int lg = lane >> 2, lc = lane & 3;
    const int row0 = blockIdx.x * 32;

    // ---- LN2: warp handles 2 rows, straight from g_x ----
    #pragma unroll
    for (int rr = 0; rr < 2; rr++) {
        const int row = wid * 2 + rr;
        const float* xr = g_x + (size_t)(row0 + row) * Dn;
        float4 v0 = *(const float4*)&xr[lane * 8];
        float4 v1 = *(const float4*)&xr[lane * 8 + 4];
        float v[8] = {v0.x, v0.y, v0.z, v0.w, v1.x, v1.y, v1.z, v1.w};
        float s = 0.f, s2 = 0.f;
        #pragma unroll
        for (int t = 0; t < 8; t++) { s += v[t]; s2 += v[t] * v[t]; }
        #pragma unroll
        for (int o = 16; o; o >>= 1) {
            s  += __shfl_xor_sync(0xffffffffu, s,  o);
            s2 += __shfl_xor_sync(0xffffffffu, s2, o);
        }
        const float mu   = s * (1.0f / Dn);
        const float var  = s2 * (1.0f / Dn) - mu * mu;
        const float rstd = rsqrtf(var + 1e-5f);
        #pragma unroll
        for (int t = 0; t < 8; t++) {
            const int c = lane * 8 + t;
            hS[row * 260 + c] = (v[t] - mu) * rstd * ln2g[c] + ln2b[c];
        }
    }
    __syncthreads();

    float acc2[2][2][4];
    #pragma unroll
    for (int mt = 0; mt < 2; mt++)
        #pragma unroll
        for (int nt = 0; nt < 2; nt++)
            #pragma unroll
            for (int e = 0; e < 4; e++) acc2[mt][nt][e] = 0.f;

    for (int half = 0; half < 2; half++) {
        // ---- ff1: warp covers 32 cols of this 512-col half ----
        float acc[2][4][4];
        #pragma unroll
        for (int mt = 0; mt < 2; mt++)
            #pragma unroll
            for (int nt = 0; nt < 4; nt++)
                #pragma unroll
                for (int e = 0; e < 4; e++) acc[mt][nt][e] = 0.f;

        for (int ks = 0; ks < 32; ks++) {
            const int kb = ks * 8;
            uint32_t ahi[2][4], alo[2][4];
            #pragma unroll
            for (int mt = 0; mt < 2; mt++) {
                const int r0 = mt * 16 + lg;
                float fa[4];
                fa[0] = hS[r0 * 260 + kb + lc];
                fa[1] = hS[(r0 + 8) * 260 + kb + lc];
                fa[2] = hS[r0 * 260 + kb + lc + 4];
                fa[3] = hS[(r0 + 8) * 260 + kb + lc + 4];
                #pragma unroll
                for (int e = 0; e < 4; e++) {
                    ahi[mt][e] = f2tf(fa[e]);
                    alo[mt][e] = f2tf(fa[e] - __uint_as_float(ahi[mt][e]));
                }
            }
            #pragma unroll
            for (int nt = 0; nt < 4; nt++) {
                const int nb = half * 512 + wid * 32 + nt * 8;
                uint32_t bhi[2], blo[2];
                bhi[0] = g_w1hi[(kb + lc) * FFn + nb + lg];
                blo[0] = g_w1lo[(kb + lc) * FFn + nb + lg];
                bhi[1] = g_w1hi[(kb + lc + 4) * FFn + nb + lg];
                blo[1] = g_w1lo[(kb + lc + 4) * FFn + nb + lg];
                #pragma unroll
                for (int mt = 0; mt < 2; mt++) {
                    mma8(acc[mt][nt], alo[mt], bhi);
                    mma8(acc[mt][nt], ahi[mt], blo);
                    mma8(acc[mt][nt], ahi[mt], bhi);
                }
            }
        }

        // ---- bias + gelu -> act ----
        #pragma unroll
        for (int mt = 0; mt < 2; mt++) {
            const int r0 = mt * 16 + lg;
            #pragma unroll
            for (int nt = 0; nt < 4; nt++) {
                const int lcol = wid * 32 + nt * 8 + lc * 2;
                const int gcol = half * 512 + lcol;
                #pragma unroll
                for (int e = 0; e < 2; e++) {
                    const float bb = ff1b[gcol + e];
                    float u0 = acc[mt][nt][e] + bb;
                    float u1 = acc[mt][nt][2 + e] + bb;
                    act[r0 * 516 + lcol + e] =
                        0.5f * u0 * (1.0f + erff(u0 * 0.70710678118654752f));
                    act[(r0 + 8) * 516 + lcol + e] =
                        0.5f * u1 * (1.0f + erff(u1 * 0.70710678118654752f));
                }
            }
        }
        __syncthreads();

        // ---- ff2 partial over this half's K=512; warp covers 16 out cols ----
        for (int ks = 0; ks < 64; ks++) {
            const int kb = ks * 8;
            uint32_t ahi[2][4], alo[2][4];
            #pragma unroll
            for (int mt = 0; mt < 2; mt++) {
                const int r0 = mt * 16 + lg;
                float fa[4];
                fa[0] = act[r0 * 516 + kb + lc];
                fa[1] = act[(r0 + 8) * 516 + kb + lc];
                fa[2] = act[r0 * 516 + kb + lc + 4];
                fa[3] = act[(r0 + 8) * 516 + kb + lc + 4];
                #pragma unroll
                for (int e = 0; e < 4; e++) {
                    ahi[mt][e] = f2tf(fa[e]);
                    alo[mt][e] = f2tf(fa[e] - __uint_as_float(ahi[mt][e]));
                }
            }
            #pragma unroll
            for (int nt = 0; nt < 2; nt++) {
                const int nb = wid * 16 + nt * 8;
                const int krow = half * 512 + kb + lc;
                uint32_t bhi[2], blo[2];
                bhi[0] = g_w2hi[krow * Dn + nb + lg];
                blo[0] = g_w2lo[krow * Dn + nb + lg];
                bhi[1] = g_w2hi[(krow + 4) * Dn + nb + lg];
                blo[1] = g_w2lo[(krow + 4) * Dn + nb + lg];
                #pragma unroll
                for (int mt = 0; mt < 2; mt++) {
                    mma8(acc2[mt][nt], alo[mt], bhi);
                    mma8(acc2[mt][nt], ahi[mt], blo);
                    mma8(acc2[mt][nt], ahi[mt], bhi);
                }
            }
        }
        __syncthreads();
    }

    // ---- epilogue: residual (reload g_x) + ff2 bias ----
    #pragma unroll
    for (int mt = 0; mt < 2; mt++) {
        const int r0 = mt * 16 + lg;
        #pragma unroll
        for (int nt = 0; nt < 2; nt++) {
            const int col = wid * 16 + nt * 8 + lc * 2;
            const float b0 = ff2b[col], b1 = ff2b[col + 1];
            const size_t i0 = (size_t)(row0 + r0) * Dn + col;
            const size_t i1 = (size_t)(row0 + r0 + 8) * Dn + col;
            out[i0]     = g_x[i0]     + acc2[mt][nt][0] + b0;
            out[i0 + 1] = g_x[i0 + 1] + acc2[mt][nt][1] + b1;
            out[i1]     = g_x[i1]     + acc2[mt][nt][2] + b0;
            out[i1 + 1] = g_x[i1 + 1] + acc2[mt][nt][3] + b1;
        }
    }
}

extern "C" void kernel_launch(void* const* d_in, const int* in_sizes, int n_in,
                              void* d_out, int out_size)
{
    const float* x_anc = (const float*)d_in[0];
    const float* x_nei = (const float*)d_in[1];
    const float* Wq    = (const float*)d_in[2];
    const float* Wk    = (const float*)d_in[3];
    const float* Wv    = (const float*)d_in[4];
    const float* Wo    = (const float*)d_in[5];
    const float* ln1g  = (const float*)d_in[6];
    const float* ln1b  = (const float*)d_in[7];
    const float* ln2g  = (const float*)d_in[8];
    const float* ln2b  = (const float*)d_in[9];
    const float* ff1w  = (const float*)d_in[10];
    const float* ff1b  = (const float*)d_in[11];
    const float* ff2w  = (const float*)d_in[12];
    const float* ff2b  = (const float*)d_in[13];
    float* out = (float*)d_out;

    static bool attr_set = false;
    if (!attr_set) {
        cudaFuncSetAttribute(attn5,    cudaFuncAttributeMaxDynamicSharedMemorySize, ATTN_SMEM);
        cudaFuncSetAttribute(ffn_mma2, cudaFuncAttributeMaxDynamicSharedMemorySize, FFN_SMEM);
        attr_set = true;
    }

    split_w<<<1024, 256>>>(ff1w, ff2w);
    attn5<<<Bn / 8, 512, ATTN_SMEM>>>(x_anc, x_nei, Wq, Wk, Wv, Wo, ln1g, ln1b);
    ffn_mma2<<<Bn / 32, 512, FFN_SMEM>>>(ln2g, ln2b, ff1b, ff2b, out);
}

// round 6
// speedup vs baseline: 5.1355x; 1.2793x over previous
#include <cuda_runtime.h>
#include <math.h>
#include <stdint.h>

#define Bn 32768
#define Dn 256
#define KN 32
#define FFn 1024

// residual after attention
__device__ float g_x[Bn * Dn];
// frag-ordered pre-split tf32 weights: uint4 {hi(b0), lo(b0), hi(b1), lo(b1)}
__device__ uint4 g_wqf[32 * 32 * 32];        // Wq: ks(32) x ntile(32) x lane(32)
__device__ uint4 g_wof[32 * 32 * 32];        // Wo
__device__ uint4 g_wkf[8 * 4 * 32 * 32];     // Wk per head: h(8) x ks(4) x ntile(32) x lane
__device__ uint4 g_w1f[32 * 128 * 32];       // ff1w: ks(32) x ntile(128) x lane
__device__ uint4 g_w2f[128 * 32 * 32];       // ff2w: ks(128) x ntile(32) x lane

// ---- attn smem layout (floats, stride 268 for bank-conflict-free frag LDS) ----
#define SM_H 0                 // [8][268]  LN1 rows
#define SM_QS 2144             // [8][268]  Q
#define SM_C 4288              // [64][268] c[a][h]
#define SM_U 21440             // [64][268] u[a][h]
#define SM_SS 38592            // [2][264] scores
#define SM_AA 39120            // [2][264] attn
#define SM_O 39648             // [8][268]
#define ATTN_SMEM (41792 * 4)

// ---- ffn smem (uint2 words) ----
#define FH_STRIDE 266
#define FA_STRIDE 522
#define FFN_SMEM ((32 * FH_STRIDE + 32 * FA_STRIDE) * 8)

__device__ __forceinline__ uint32_t f2tf(float f) {
    uint32_t u;
    asm("cvt.rna.tf32.f32 %0, %1;" : "=r"(u) : "f"(f));
    return u;
}

__device__ __forceinline__ void mma8(float* c, const uint32_t* a, const uint32_t* b) {
    asm volatile(
        "mma.sync.aligned.m16n8k8.row.col.f32.tf32.tf32.f32 "
        "{%0,%1,%2,%3}, {%4,%5,%6,%7}, {%8,%9}, {%0,%1,%2,%3};"
        : "+f"(c[0]), "+f"(c[1]), "+f"(c[2]), "+f"(c[3])
        : "r"(a[0]), "r"(a[1]), "r"(a[2]), "r"(a[3]), "r"(b[0]), "r"(b[1]));
}

__device__ __forceinline__ uint4 splitpair(float b0, float b1) {
    uint4 r;
    r.x = f2tf(b0); r.y = f2tf(b0 - __uint_as_float(r.x));
    r.z = f2tf(b1); r.w = f2tf(b1 - __uint_as_float(r.z));
    return r;
}

// ---------------------------------------------------------------------------
// setup: build all frag-ordered pre-split weight images.
// ---------------------------------------------------------------------------
__global__ void split_all(
    const float* __restrict__ Wq, const float* __restrict__ Wk,
    const float* __restrict__ Wo,
    const float* __restrict__ ff1w, const float* __restrict__ ff2w)
{
    int gid = blockIdx.x * 256 + threadIdx.x;
    if (gid < 32768) {                                    // Wq
        int lane = gid & 31, t = gid >> 5;
        int ntile = t & 31, ks = t >> 5;
        int lg = lane >> 2, lc = lane & 3;
        int k0 = ks * 8 + lc, n = ntile * 8 + lg;
        g_wqf[gid] = splitpair(Wq[k0 * 256 + n], Wq[(k0 + 4) * 256 + n]);
    } else if (gid < 65536) {                             // Wo
        int e = gid - 32768;
        int lane = e & 31, t = e >> 5;
        int ntile = t & 31, ks = t >> 5;
        int lg = lane >> 2, lc = lane & 3;
        int k0 = ks * 8 + lc, n = ntile * 8 + lg;
        g_wof[e] = splitpair(Wo[k0 * 256 + n], Wo[(k0 + 4) * 256 + n]);
    } else if (gid < 98304) {                             // Wk (per head, transposed)
        int e = gid - 65536;
        int lane = e & 31, t = e >> 5;
        int ntile = t & 31, hk = t >> 5;                  // hk = h*4 + ks
        int h = hk >> 2, ks = hk & 3;
        int lg = lane >> 2, lc = lane & 3;
        int k0 = ks * 8 + lc, n = ntile * 8 + lg;
        g_wkf[e] = splitpair(Wk[n * 256 + h * 32 + k0],
                             Wk[n * 256 + h * 32 + k0 + 4]);
    } else if (gid < 229376) {                            // ff1w
        int e = gid - 98304;
        int lane = e & 31, t = e >> 5;
        int ntile = t & 127, ks = t >> 7;
        int lg = lane >> 2, lc = lane & 3;
        int k0 = ks * 8 + lc, n = ntile * 8 + lg;
        g_w1f[e] = splitpair(ff1w[k0 * FFn + n], ff1w[(k0 + 4) * FFn + n]);
    } else if (gid < 360448) {                            // ff2w
        int e = gid - 229376;
        int lane = e & 31, t = e >> 5;
        int ntile = t & 31, ks = t >> 5;
        int lg = lane >> 2, lc = lane & 3;
        int k0 = ks * 8 + lc, n = ntile * 8 + lg;
        g_w2f[e] = splitpair(ff2w[k0 * 256 + n], ff2w[(k0 + 4) * 256 + n]);
    }
}

// ---------------------------------------------------------------------------
// Attention: LN1 -> Q(mma) -> c(mma) -> scores -> softmax -> u -> Wv -> Wo(mma).
// 8 anchors / CTA, 512 threads.
// ---------------------------------------------------------------------------
__global__ __launch_bounds__(512, 1) void attn6(
    const float* __restrict__ x_anc, const float* __restrict__ x_nei,
    const float* __restrict__ Wv,
    const float* __restrict__ g1, const float* __restrict__ b1)
{
    extern __shared__ float sf[];
    float* hS = sf + SM_H;
    float* qS = sf + SM_QS;
    float* cS = sf + SM_C;
    float* uS = sf + SM_U;
    float* sS = sf + SM_SS;
    float* aS = sf + SM_AA;
    float* oS = sf + SM_O;

    const int tid = threadIdx.x, wid = tid >> 5, lane = tid & 31;
    const int lg = lane >> 2, lc = lane & 3;
    const int j2 = tid & 255;
    const int a0 = (tid >> 8) * 4;
    const int b0 = blockIdx.x * 8;

    // ---- LN1: warps 0-7, one row each ----
    if (wid < 8) {
        const float* xr = x_anc + (size_t)(b0 + wid) * Dn;
        float4 v0 = *(const float4*)&xr[lane * 8];
        float4 v1 = *(const float4*)&xr[lane * 8 + 4];
        float v[8] = {v0.x, v0.y, v0.z, v0.w, v1.x, v1.y, v1.z, v1.w};
        float s = 0.f, s2 = 0.f;
        #pragma unroll
        for (int t = 0; t < 8; t++) { s += v[t]; s2 += v[t] * v[t]; }
        #pragma unroll
        for (int o = 16; o; o >>= 1) {
            s  += __shfl_xor_sync(0xffffffffu, s,  o);
            s2 += __shfl_xor_sync(0xffffffffu, s2, o);
        }
        const float mu   = s * (1.0f / Dn);
        const float var  = s2 * (1.0f / Dn) - mu * mu;
        const float rstd = rsqrtf(var + 1e-5f);
        #pragma unroll
        for (int t = 0; t < 8; t++) {
            const int c = lane * 8 + t;
            hS[wid * 268 + c] = (v[t] - mu) * rstd * g1[c] + b1[c];
        }
    }
    __syncthreads();

    // ---- Q = h @ Wq via mma (M=8 in frag rows lg; rows 8-15 are zero regs) ----
    {
        float acc[2][4] = {{0.f,0.f,0.f,0.f},{0.f,0.f,0.f,0.f}};
        for (int ks = 0; ks < 32; ks++) {
            const int kb = ks * 8;
            float q0 = hS[lg * 268 + kb + lc];
            float q1 = hS[lg * 268 + kb + lc + 4];
            uint32_t ahi[4], alo[4];
            ahi[0] = f2tf(q0); alo[0] = f2tf(q0 - __uint_as_float(ahi[0]));
            ahi[2] = f2tf(q1); alo[2] = f2tf(q1 - __uint_as_float(ahi[2]));
            ahi[1] = alo[1] = ahi[3] = alo[3] = 0u;
            #pragma unroll
            for (int nt = 0; nt < 2; nt++) {
                uint4 v = g_wqf[(ks * 32 + wid * 2 + nt) * 32 + lane];
                uint32_t bhi[2] = {v.x, v.z}, blo[2] = {v.y, v.w};
                mma8(acc[nt], alo, bhi);
                mma8(acc[nt], ahi, blo);
                mma8(acc[nt], ahi, bhi);
            }
        }
        #pragma unroll
        for (int nt = 0; nt < 2; nt++) {
            const int col = wid * 16 + nt * 8 + lc * 2;
            qS[lg * 268 + col]     = acc[nt][0];
            qS[lg * 268 + col + 1] = acc[nt][1];
        }
    }
    __syncthreads();

    // ---- c[a][h][:] = Q[a][h-slice] @ Wk[:, h-slice]^T via mma per head ----
    {
        #pragma unroll
        for (int h = 0; h < 8; h++) {
            float acc[2][4] = {{0.f,0.f,0.f,0.f},{0.f,0.f,0.f,0.f}};
            #pragma unroll
            for (int ks = 0; ks < 4; ks++) {
                const int kb = ks * 8;
                float q0 = qS[lg * 268 + h * 32 + kb + lc];
                float q1 = qS[lg * 268 + h * 32 + kb + lc + 4];
                uint32_t ahi[4], alo[4];
                ahi[0] = f2tf(q0); alo[0] = f2tf(q0 - __uint_as_float(ahi[0]));
                ahi[2] = f2tf(q1); alo[2] = f2tf(q1 - __uint_as_float(ahi[2]));
                ahi[1] = alo[1] = ahi[3] = alo[3] = 0u;
                #pragma unroll
                for (int nt = 0; nt < 2; nt++) {
                    uint4 v = g_wkf[((h * 4 + ks) * 32 + wid * 2 + nt) * 32 + lane];
                    uint32_t bhi[2] = {v.x, v.z}, blo[2] = {v.y, v.w};
                    mma8(acc[nt], alo, bhi);
                    mma8(acc[nt], ahi, blo);
                    mma8(acc[nt], ahi, bhi);
                }
            }
            #pragma unroll
            for (int nt = 0; nt < 2; nt++) {
                const int col = wid * 16 + nt * 8 + lc * 2;
                cS[(lg * 8 + h) * 268 + col]     = acc[nt][0];
                cS[(lg * 8 + h) * 268 + col + 1] = acc[nt][1];
            }
        }
    }
    __syncthreads();

    // ---- anchor pairs: warp-group g handles anchor 2p+g ----
    const int g = wid >> 3;
    const int wid2 = wid & 7;
    const int kk = j2 >> 3, ss = j2 & 7;
    for (int p = 0; p < 4; p++) {
        const int a = 2 * p + g;
        const float* xb = x_nei + (size_t)(b0 + a) * (KN * Dn);

        // scores
        float pr[8];
        #pragma unroll
        for (int h = 0; h < 8; h++) pr[h] = 0.f;
        #pragma unroll
        for (int i = 0; i < 8; i++) {
            float4 x4 = *(const float4*)&xb[kk * Dn + ss * 4 + i * 32];
            #pragma unroll
            for (int h = 0; h < 8; h++) {
                float4 c4 = *(const float4*)&cS[(a * 8 + h) * 268 + ss * 4 + i * 32];
                pr[h] = fmaf(x4.x, c4.x, fmaf(x4.y, c4.y,
                        fmaf(x4.z, c4.z, fmaf(x4.w, c4.w, pr[h]))));
            }
        }
        #pragma unroll
        for (int o = 1; o <= 4; o <<= 1) {
            #pragma unroll
            for (int h = 0; h < 8; h++)
                pr[h] += __shfl_xor_sync(0xffffffffu, pr[h], o);
        }
        sS[g * 264 + ss * 33 + kk] = pr[ss];
        __syncthreads();

        // softmax
        {
            float sc = sS[g * 264 + wid2 * 33 + lane] * 0.17677669529663687f;
            float m = sc;
            #pragma unroll
            for (int o = 16; o; o >>= 1)
                m = fmaxf(m, __shfl_xor_sync(0xffffffffu, m, o));
            float e = expf(sc - m), es = e;
            #pragma unroll
            for (int o = 16; o; o >>= 1)
                es += __shfl_xor_sync(0xffffffffu, es, o);
            aS[g * 264 + wid2 * 33 + lane] = e / es;
        }
        __syncthreads();

        // u
        {
            float xr2[32];
            #pragma unroll
            for (int k = 0; k < KN; k++) xr2[k] = xb[k * Dn + j2];
            float u[8];
            #pragma unroll
            for (int h = 0; h < 8; h++) u[h] = 0.f;
            #pragma unroll
            for (int k = 0; k < KN; k++) {
                #pragma unroll
                for (int h = 0; h < 8; h++)
                    u[h] = fmaf(aS[g * 264 + h * 33 + k], xr2[k], u[h]);
            }
            #pragma unroll
            for (int h = 0; h < 8; h++)
                uS[(a * 8 + h) * 268 + j2] = u[h];
        }
        __syncthreads();
    }

    // ---- out[a][j2] = sum_d u[a][h(j2)][d] * Wv[d][j2]  (scalar, broadcast LDS) ----
    {
        const int hj = j2 >> 5;
        float ot[4] = {0.f, 0.f, 0.f, 0.f};
        for (int d = 0; d < Dn; d += 4) {
            const float w0 = Wv[(d + 0) * Dn + j2];
            const float w1 = Wv[(d + 1) * Dn + j2];
            const float w2 = Wv[(d + 2) * Dn + j2];
            const float w3 = Wv[(d + 3) * Dn + j2];
            #pragma unroll
            for (int a = 0; a < 4; a++) {
                float4 u4 = *(const float4*)&uS[((a0 + a) * 8 + hj) * 268 + d];
                ot[a] = fmaf(u4.x, w0, fmaf(u4.y, w1, fmaf(u4.z, w2, fmaf(u4.w, w3, ot[a]))));
            }
        }
        #pragma unroll
        for (int a = 0; a < 4; a++) oS[(a0 + a) * 268 + j2] = ot[a];
    }
    __syncthreads();

    // ---- x = x_anc + oS @ Wo via mma ----
    {
        float acc[2][4] = {{0.f,0.f,0.f,0.f},{0.f,0.f,0.f,0.f}};
        for (int ks = 0; ks < 32; ks++) {
            const int kb = ks * 8;
            float q0 = oS[lg * 268 + kb + lc];
            float q1 = oS[lg * 268 + kb + lc + 4];
            uint32_t ahi[4], alo[4];
            ahi[0] = f2tf(q0); alo[0] = f2tf(q0 - __uint_as_float(ahi[0]));
            ahi[2] = f2tf(q1); alo[2] = f2tf(q1 - __uint_as_float(ahi[2]));
            ahi[1] = alo[1] = ahi[3] = alo[3] = 0u;
            #pragma unroll
            for (int nt = 0; nt < 2; nt++) {
                uint4 v = g_wof[(ks * 32 + wid * 2 + nt) * 32 + lane];
                uint32_t bhi[2] = {v.x, v.z}, blo[2] = {v.y, v.w};
                mma8(acc[nt], alo, bhi);
                mma8(acc[nt], ahi, blo);
                mma8(acc[nt], ahi, bhi);
            }
        }
        #pragma unroll
        for (int nt = 0; nt < 2; nt++) {
            const int col = wid * 16 + nt * 8 + lc * 2;
            const size_t idx = (size_t)(b0 + lg) * Dn + col;
            g_x[idx]     = x_anc[idx]     + acc[nt][0];
            g_x[idx + 1] = x_anc[idx + 1] + acc[nt][1];
        }
    }
}

// ---------------------------------------------------------------------------
// FFN: LN2 -> ff1(mma)+gelu -> ff2(mma)+residual. 32 rows / CTA, 512 threads.
// A-operands pre-split to interleaved hi/lo uint2 smem; B frag-ordered gmem.
// ---------------------------------------------------------------------------
__global__ __launch_bounds__(512, 1) void ffn_mma3(
    const float* __restrict__ ln2g, const float* __restrict__ ln2b,
    const float* __restrict__ ff1b, const float* __restrict__ ff2b,
    float* __restrict__ out)
{
    extern __shared__ uint2 su[];
    uint2* hHL   = su;                          // [32][266]
    uint2* actHL = su + 32 * FH_STRIDE;         // [32][522]

    const int tid = threadIdx.x, wid = tid >> 5, lane = tid & 31;
    const int lg = lane >> 2, lc = lane & 3;
    const int row0 = blockIdx.x * 32;

    // ---- LN2: warp handles 2 rows; store split hi/lo ----
    #pragma unroll
    for (int rr = 0; rr < 2; rr++) {
        const int row = wid * 2 + rr;
        const float* xr = g_x + (size_t)(row0 + row) * Dn;
        float4 v0 = *(const float4*)&xr[lane * 8];
        float4 v1 = *(const float4*)&xr[lane * 8 + 4];
        float v[8] = {v0.x, v0.y, v0.z, v0.w, v1.x, v1.y, v1.z, v1.w};
        float s = 0.f, s2 = 0.f;
        #pragma unroll
        for (int t = 0; t < 8; t++) { s += v[t]; s2 += v[t] * v[t]; }
        #pragma unroll
        for (int o = 16; o; o >>= 1) {
            s  += __shfl_xor_sync(0xffffffffu, s,  o);
            s2 += __shfl_xor_sync(0xffffffffu, s2, o);
        }
        const float mu   = s * (1.0f / Dn);
        const float var  = s2 * (1.0f / Dn) - mu * mu;
        const float rstd = rsqrtf(var + 1e-5f);
        #pragma unroll
        for (int t = 0; t < 8; t++) {
            const int c = lane * 8 + t;
            float hv = (v[t] - mu) * rstd * ln2g[c] + ln2b[c];
            uint32_t hi = f2tf(hv);
            hHL[row * FH_STRIDE + c] = make_uint2(hi, f2tf(hv - __uint_as_float(hi)));
        }
    }
    __syncthreads();

    float acc2[2][2][4];
    #pragma unroll
    for (int mt = 0; mt < 2; mt++)
        #pragma unroll
        for (int nt = 0; nt < 2; nt++)
            #pragma unroll
            for (int e = 0; e < 4; e++) acc2[mt][nt][e] = 0.f;

    for (int half = 0; half < 2; half++) {
        float acc[2][4][4];
        #pragma unroll
        for (int mt = 0; mt < 2; mt++)
            #pragma unroll
            for (int nt = 0; nt < 4; nt++)
                #pragma unroll
                for (int e = 0; e < 4; e++) acc[mt][nt][e] = 0.f;

        // ---- ff1 ----
        for (int ks = 0; ks < 32; ks++) {
            const int kb = ks * 8;
            uint32_t ahi[2][4], alo[2][4];
            #pragma unroll
            for (int mt = 0; mt < 2; mt++) {
                const int r0 = mt * 16 + lg;
                uint2 p0 = hHL[r0 * FH_STRIDE + kb + lc];
                uint2 p1 = hHL[(r0 + 8) * FH_STRIDE + kb + lc];
                uint2 p2 = hHL[r0 * FH_STRIDE + kb + lc + 4];
                uint2 p3 = hHL[(r0 + 8) * FH_STRIDE + kb + lc + 4];
                ahi[mt][0] = p0.x; alo[mt][0] = p0.y;
                ahi[mt][1] = p1.x; alo[mt][1] = p1.y;
                ahi[mt][2] = p2.x; alo[mt][2] = p2.y;
                ahi[mt][3] = p3.x; alo[mt][3] = p3.y;
            }
            #pragma unroll
            for (int nt = 0; nt < 4; nt++) {
                const int ntile = half * 64 + wid * 4 + nt;
                uint4 v = g_w1f[(ks * 128 + ntile) * 32 + lane];
                uint32_t bhi[2] = {v.x, v.z}, blo[2] = {v.y, v.w};
                #pragma unroll
                for (int mt = 0; mt < 2; mt++) {
                    mma8(acc[mt][nt], alo[mt], bhi);
                    mma8(acc[mt][nt], ahi[mt], blo);
                    mma8(acc[mt][nt], ahi[mt], bhi);
                }
            }
        }

        // ---- bias + gelu -> split act ----
        #pragma unroll
        for (int mt = 0; mt < 2; mt++) {
            const int r0 = mt * 16 + lg;
            #pragma unroll
            for (int nt = 0; nt < 4; nt++) {
                const int lcol = wid * 32 + nt * 8 + lc * 2;
                const int gcol = half * 512 + lcol;
                #pragma unroll
                for (int e = 0; e < 2; e++) {
                    const float bb = ff1b[gcol + e];
                    float u0 = acc[mt][nt][e] + bb;
                    float u1 = acc[mt][nt][2 + e] + bb;
                    float g0 = 0.5f * u0 * (1.0f + erff(u0 * 0.70710678118654752f));
                    float g1v = 0.5f * u1 * (1.0f + erff(u1 * 0.70710678118654752f));
                    uint32_t h0 = f2tf(g0), h1 = f2tf(g1v);
                    actHL[r0 * FA_STRIDE + lcol + e] =
                        make_uint2(h0, f2tf(g0 - __uint_as_float(h0)));
                    actHL[(r0 + 8) * FA_STRIDE + lcol + e] =
                        make_uint2(h1, f2tf(g1v - __uint_as_float(h1)));
                }
            }
        }
        __syncthreads();

        // ---- ff2 partial over this half's K=512 ----
        for (int ks = 0; ks < 64; ks++) {
            const int kb = ks * 8;
            uint32_t ahi[2][4], alo[2][4];
            #pragma unroll
            for (int mt = 0; mt < 2; mt++) {
                const int r0 = mt * 16 + lg;
                uint2 p0 = actHL[r0 * FA_STRIDE + kb + lc];
                uint2 p1 = actHL[(r0 + 8) * FA_STRIDE + kb + lc];
                uint2 p2 = actHL[r0 * FA_STRIDE + kb + lc + 4];
                uint2 p3 = actHL[(r0 + 8) * FA_STRIDE + kb + lc + 4];
                ahi[mt][0] = p0.x; alo[mt][0] = p0.y;
                ahi[mt][1] = p1.x; alo[mt][1] = p1.y;
                ahi[mt][2] = p2.x; alo[mt][2] = p2.y;
                ahi[mt][3] = p3.x; alo[mt][3] = p3.y;
            }
            #pragma unroll
            for (int nt = 0; nt < 2; nt++) {
                const int ntile = wid * 2 + nt;
                const int ksg = half * 64 + ks;
                uint4 v = g_w2f[(ksg * 32 + ntile) * 32 + lane];
                uint32_t bhi[2] = {v.x, v.z}, blo[2] = {v.y, v.w};
                #pragma unroll
                for (int mt = 0; mt < 2; mt++) {
                    mma8(acc2[mt][nt], alo[mt], bhi);
                    mma8(acc2[mt][nt], ahi[mt], blo);
                    mma8(acc2[mt][nt], ahi[mt], bhi);
                }
            }
        }
        __syncthreads();
    }

    // ---- epilogue: residual + ff2 bias ----
    #pragma unroll
    for (int mt = 0; mt < 2; mt++) {
        const int r0 = mt * 16 + lg;
        #pragma unroll
        for (int nt = 0; nt < 2; nt++) {
            const int col = wid * 16 + nt * 8 + lc * 2;
            const float b0 = ff2b[col], b1 = ff2b[col + 1];
            const size_t i0 = (size_t)(row0 + r0) * Dn + col;
            const size_t i1 = (size_t)(row0 + r0 + 8) * Dn + col;
            out[i0]     = g_x[i0]     + acc2[mt][nt][0] + b0;
            out[i0 + 1] = g_x[i0 + 1] + acc2[mt][nt][1] + b1;
            out[i1]     = g_x[i1]     + acc2[mt][nt][2] + b0;
            out[i1 + 1] = g_x[i1 + 1] + acc2[mt][nt][3] + b1;
        }
    }
}

extern "C" void kernel_launch(void* const* d_in, const int* in_sizes, int n_in,
                              void* d_out, int out_size)
{
    const float* x_anc = (const float*)d_in[0];
    const float* x_nei = (const float*)d_in[1];
    const float* Wq    = (const float*)d_in[2];
    const float* Wk    = (const float*)d_in[3];
    const float* Wv    = (const float*)d_in[4];
    const float* Wo    = (const float*)d_in[5];
    const float* ln1g  = (const float*)d_in[6];
    const float* ln1b  = (const float*)d_in[7];
    const float* ln2g  = (const float*)d_in[8];
    const float* ln2b  = (const float*)d_in[9];
    const float* ff1w  = (const float*)d_in[10];
    const float* ff1b  = (const float*)d_in[11];
    const float* ff2w  = (const float*)d_in[12];
    const float* ff2b  = (const float*)d_in[13];
    float* out = (float*)d_out;

    static bool attr_set = false;
    if (!attr_set) {
        cudaFuncSetAttribute(attn6,    cudaFuncAttributeMaxDynamicSharedMemorySize, ATTN_SMEM);
        cudaFuncSetAttribute(ffn_mma3, cudaFuncAttributeMaxDynamicSharedMemorySize, FFN_SMEM);
        attr_set = true;
    }

    split_all<<<1408, 256>>>(Wq, Wk, Wo, ff1w, ff2w);
    attn6<<<Bn / 8, 512, ATTN_SMEM>>>(x_anc, x_nei, Wv, ln1g, ln1b);
    ffn_mma3<<<Bn / 32, 512, FFN_SMEM>>>(ln2g, ln2b, ff1b, ff2b, out);
}

// round 8
// speedup vs baseline: 5.5262x; 1.0761x over previous
#include <cuda_runtime.h>
#include <math.h>
#include <stdint.h>

#define Bn 32768
#define Dn 256
#define KN 32
#define FFn 1024

// residual after attention
__device__ float g_x[Bn * Dn];
// frag-ordered pre-split tf32 weights: uint4 {hi(b0), lo(b0), hi(b1), lo(b1)}
__device__ uint4 g_wqf[32 * 32 * 32];
__device__ uint4 g_wof[32 * 32 * 32];
__device__ uint4 g_wkf[8 * 4 * 32 * 32];
__device__ uint4 g_w1f[32 * 128 * 32];
__device__ uint4 g_w2f[128 * 32 * 32];

// ---- attn smem layout (floats); cS/uS and qS/oS aliased ----
#define SM_H 0                 // [8][268]  LN1 rows
#define SM_QS 2144             // [8][268]  Q  (later: attn-out rows oS)
#define SM_C 4288              // [64][268] c  (later: u)
#define SM_SS 21440            // [8][8][33] scores
#define SM_AA 23552            // [8][8][33] attn
#define ATTN_SMEM (25664 * 4)  // 102,656 B -> 2 CTAs/SM

// ---- ffn smem (uint2 words) ----
#define FH_STRIDE 266
#define FA_STRIDE 522
#define FFN_SMEM ((32 * FH_STRIDE + 32 * FA_STRIDE) * 8)

__device__ __forceinline__ uint32_t f2tf(float f) {
    uint32_t u;
    asm("cvt.rna.tf32.f32 %0, %1;" : "=r"(u) : "f"(f));
    return u;
}

__device__ __forceinline__ void mma8(float* c, const uint32_t* a, const uint32_t* b) {
    asm volatile(
        "mma.sync.aligned.m16n8k8.row.col.f32.tf32.tf32.f32 "
        "{%0,%1,%2,%3}, {%4,%5,%6,%7}, {%8,%9}, {%0,%1,%2,%3};"
        : "+f"(c[0]), "+f"(c[1]), "+f"(c[2]), "+f"(c[3])
        : "r"(a[0]), "r"(a[1]), "r"(a[2]), "r"(a[3]), "r"(b[0]), "r"(b[1]));
}

__device__ __forceinline__ uint4 splitpair(float b0, float b1) {
    uint4 r;
    r.x = f2tf(b0); r.y = f2tf(b0 - __uint_as_float(r.x));
    r.z = f2tf(b1); r.w = f2tf(b1 - __uint_as_float(r.z));
    return r;
}

// ---------------------------------------------------------------------------
__global__ void split_all(
    const float* __restrict__ Wq, const float* __restrict__ Wk,
    const float* __restrict__ Wo,
    const float* __restrict__ ff1w, const float* __restrict__ ff2w)
{
    int gid = blockIdx.x * 256 + threadIdx.x;
    if (gid < 32768) {
        int lane = gid & 31, t = gid >> 5;
        int ntile = t & 31, ks = t >> 5;
        int lg = lane >> 2, lc = lane & 3;
        int k0 = ks * 8 + lc, n = ntile * 8 + lg;
        g_wqf[gid] = splitpair(Wq[k0 * 256 + n], Wq[(k0 + 4) * 256 + n]);
    } else if (gid < 65536) {
        int e = gid - 32768;
        int lane = e & 31, t = e >> 5;
        int ntile = t & 31, ks = t >> 5;
        int lg = lane >> 2, lc = lane & 3;
        int k0 = ks * 8 + lc, n = ntile * 8 + lg;
        g_wof[e] = splitpair(Wo[k0 * 256 + n], Wo[(k0 + 4) * 256 + n]);
    } else if (gid < 98304) {
        int e = gid - 65536;
        int lane = e & 31, t = e >> 5;
        int ntile = t & 31, hk = t >> 5;
        int h = hk >> 2, ks = hk & 3;
        int lg = lane >> 2, lc = lane & 3;
        int k0 = ks * 8 + lc, n = ntile * 8 + lg;
        g_wkf[e] = splitpair(Wk[n * 256 + h * 32 + k0],
                             Wk[n * 256 + h * 32 + k0 + 4]);
    } else if (gid < 229376) {
        int e = gid - 98304;
        int lane = e & 31, t = e >> 5;
        int ntile = t & 127, ks = t >> 7;
        int lg = lane >> 2, lc = lane & 3;
        int k0 = ks * 8 + lc, n = ntile * 8 + lg;
        g_w1f[e] = splitpair(ff1w[k0 * FFn + n], ff1w[(k0 + 4) * FFn + n]);
    } else if (gid < 360448) {
        int e = gid - 229376;
        int lane = e & 31, t = e >> 5;
        int ntile = t & 31, ks = t >> 5;
        int lg = lane >> 2, lc = lane & 3;
        int k0 = ks * 8 + lc, n = ntile * 8 + lg;
        g_w2f[e] = splitpair(ff2w[k0 * 256 + n], ff2w[(k0 + 4) * 256 + n]);
    }
}

// ---------------------------------------------------------------------------
// Attention, flattened phases, 2 CTAs/SM. 8 anchors / CTA, 512 threads.
// ---------------------------------------------------------------------------
__global__ __launch_bounds__(512, 2) void attn7(
    const float* __restrict__ x_anc, const float* __restrict__ x_nei,
    const float* __restrict__ Wv,
    const float* __restrict__ g1, const float* __restrict__ b1)
{
    extern __shared__ float sf[];
    float* hS = sf + SM_H;
    float* qS = sf + SM_QS;      // later oS
    float* cS = sf + SM_C;       // later uS
    float* sS = sf + SM_SS;
    float* aS = sf + SM_AA;
    float* uS = cS;
    float* oS = qS;

    const int tid = threadIdx.x, wid = tid >> 5, lane = tid & 31;
    const int lg = lane >> 2, lc = lane & 3;
    const int j2 = tid & 255;
    const int a0 = (tid >> 8) * 4;
    const int b0 = blockIdx.x * 8;

    // ---- LN1: warps 0-7, one row each ----
    if (wid < 8) {
        const float* xr = x_anc + (size_t)(b0 + wid) * Dn;
        float4 v0 = *(const float4*)&xr[lane * 8];
        float4 v1 = *(const float4*)&xr[lane * 8 + 4];
        float v[8] = {v0.x, v0.y, v0.z, v0.w, v1.x, v1.y, v1.z, v1.w};
        float s = 0.f, s2 = 0.f;
        #pragma unroll
        for (int t = 0; t < 8; t++) { s += v[t]; s2 += v[t] * v[t]; }
        #pragma unroll
        for (int o = 16; o; o >>= 1) {
            s  += __shfl_xor_sync(0xffffffffu, s,  o);
            s2 += __shfl_xor_sync(0xffffffffu, s2, o);
        }
        const float mu   = s * (1.0f / Dn);
        const float var  = s2 * (1.0f / Dn) - mu * mu;
        const float rstd = rsqrtf(var + 1e-5f);
        #pragma unroll
        for (int t = 0; t < 8; t++) {
            const int c = lane * 8 + t;
            hS[wid * 268 + c] = (v[t] - mu) * rstd * g1[c] + b1[c];
        }
    }
    __syncthreads();

    // ---- Q = h @ Wq via mma ----
    {
        float acc[2][4] = {{0.f,0.f,0.f,0.f},{0.f,0.f,0.f,0.f}};
        for (int ks = 0; ks < 32; ks++) {
            const int kb = ks * 8;
            float q0 = hS[lg * 268 + kb + lc];
            float q1 = hS[lg * 268 + kb + lc + 4];
            uint32_t ahi[4], alo[4];
            ahi[0] = f2tf(q0); alo[0] = f2tf(q0 - __uint_as_float(ahi[0]));
            ahi[2] = f2tf(q1); alo[2] = f2tf(q1 - __uint_as_float(ahi[2]));
            ahi[1] = alo[1] = ahi[3] = alo[3] = 0u;
            #pragma unroll
            for (int nt = 0; nt < 2; nt++) {
                uint4 v = g_wqf[(ks * 32 + wid * 2 + nt) * 32 + lane];
                uint32_t bhi[2] = {v.x, v.z}, blo[2] = {v.y, v.w};
                mma8(acc[nt], alo, bhi);
                mma8(acc[nt], ahi, blo);
                mma8(acc[nt], ahi, bhi);
            }
        }
        __syncthreads();
        #pragma unroll
        for (int nt = 0; nt < 2; nt++) {
            const int col = wid * 16 + nt * 8 + lc * 2;
            qS[lg * 268 + col]     = acc[nt][0];
            qS[lg * 268 + col + 1] = acc[nt][1];
        }
    }
    __syncthreads();

    // ---- c[a][h][:] via mma per head ----
    {
        #pragma unroll
        for (int h = 0; h < 8; h++) {
            float acc[2][4] = {{0.f,0.f,0.f,0.f},{0.f,0.f,0.f,0.f}};
            #pragma unroll
            for (int ks = 0; ks < 4; ks++) {
                const int kb = ks * 8;
                float q0 = qS[lg * 268 + h * 32 + kb + lc];
                float q1 = qS[lg * 268 + h * 32 + kb + lc + 4];
                uint32_t ahi[4], alo[4];
                ahi[0] = f2tf(q0); alo[0] = f2tf(q0 - __uint_as_float(ahi[0]));
                ahi[2] = f2tf(q1); alo[2] = f2tf(q1 - __uint_as_float(ahi[2]));
                ahi[1] = alo[1] = ahi[3] = alo[3] = 0u;
                #pragma unroll
                for (int nt = 0; nt < 2; nt++) {
                    uint4 v = g_wkf[((h * 4 + ks) * 32 + wid * 2 + nt) * 32 + lane];
                    uint32_t bhi[2] = {v.x, v.z}, blo[2] = {v.y, v.w};
                    mma8(acc[nt], alo, bhi);
                    mma8(acc[nt], ahi, blo);
                    mma8(acc[nt], ahi, bhi);
                }
            }
            #pragma unroll
            for (int nt = 0; nt < 2; nt++) {
                const int col = wid * 16 + nt * 8 + lc * 2;
                cS[(lg * 8 + h) * 268 + col]     = acc[nt][0];
                cS[(lg * 8 + h) * 268 + col + 1] = acc[nt][1];
            }
        }
    }
    __syncthreads();

    // ---- scores for ALL 8 anchors in one phase ----
    // warp-pair = anchor; within 64 threads: kk2 = t6>>1 (neighbor), ss2 = t6&1.
    // Each thread covers 128 of the 256 d'-elements (32 float4s, interleaved
    // by 4-blocks with its ss2-partner); shfl-xor-1 completes the dot product.
    {
        const int t6 = tid & 63;
        const int aa = tid >> 6;
        const int kk2 = t6 >> 1;
        const int ss2 = t6 & 1;
        const float* xb = x_nei + (size_t)(b0 + aa) * (KN * Dn) + kk2 * Dn;

        float pr[8];
        #pragma unroll
        for (int h = 0; h < 8; h++) pr[h] = 0.f;
        #pragma unroll
        for (int i = 0; i < 32; i++) {
            float4 x4 = *(const float4*)&xb[ss2 * 4 + i * 8];
            #pragma unroll
            for (int h = 0; h < 8; h++) {
                float4 c4 = *(const float4*)&cS[(aa * 8 + h) * 268 + ss2 * 4 + i * 8];
                pr[h] = fmaf(x4.x, c4.x, fmaf(x4.y, c4.y,
                        fmaf(x4.z, c4.z, fmaf(x4.w, c4.w, pr[h]))));
            }
        }
        #pragma unroll
        for (int h = 0; h < 8; h++)
            pr[h] += __shfl_xor_sync(0xffffffffu, pr[h], 1);
        #pragma unroll
        for (int t = 0; t < 4; t++) {
            const int h = ss2 * 4 + t;
            sS[(aa * 8 + h) * 33 + kk2] = pr[h];
        }
    }
    __syncthreads();

    // ---- softmax: warp handles 4 (a,h) rows ----
    {
        #pragma unroll
        for (int rr = 0; rr < 4; rr++) {
            const int r = wid * 4 + rr;
            float sc = sS[r * 33 + lane] * 0.17677669529663687f;
            float m = sc;
            #pragma unroll
            for (int o = 16; o; o >>= 1)
                m = fmaxf(m, __shfl_xor_sync(0xffffffffu, m, o));
            float e = expf(sc - m), es = e;
            #pragma unroll
            for (int o = 16; o; o >>= 1)
                es += __shfl_xor_sync(0xffffffffu, es, o);
            aS[r * 33 + lane] = e / es;
        }
    }
    __syncthreads();

    // ---- u for all anchors: thread j2 covers col j2 for 4 anchors ----
    {
        #pragma unroll
        for (int a = 0; a < 4; a++) {
            const int ag = a0 + a;
            const float* xb = x_nei + (size_t)(b0 + ag) * (KN * Dn) + j2;
            float u[8];
            #pragma unroll
            for (int h = 0; h < 8; h++) u[h] = 0.f;
            #pragma unroll
            for (int kc = 0; kc < 4; kc++) {
                float xr[8];
                #pragma unroll
                for (int t = 0; t < 8; t++) xr[t] = xb[(kc * 8 + t) * Dn];
                #pragma unroll
                for (int t = 0; t < 8; t++) {
                    const int k = kc * 8 + t;
                    #pragma unroll
                    for (int h = 0; h < 8; h++)
                        u[h] = fmaf(aS[(ag * 8 + h) * 33 + k], xr[t], u[h]);
                }
            }
            #pragma unroll
            for (int h = 0; h < 8; h++)
                uS[(ag * 8 + h) * 268 + j2] = u[h];
        }
    }
    __syncthreads();

    // ---- out[a][j2] = sum_d u[a][h(j2)][d] * Wv[d][j2] ----
    {
        const int hj = j2 >> 5;
        float ot[4] = {0.f, 0.f, 0.f, 0.f};
        for (int d = 0; d < Dn; d += 4) {
            const float w0 = Wv[(d + 0) * Dn + j2];
            const float w1 = Wv[(d + 1) * Dn + j2];
            const float w2 = Wv[(d + 2) * Dn + j2];
            const float w3 = Wv[(d + 3) * Dn + j2];
            #pragma unroll
            for (int a = 0; a < 4; a++) {
                float4 u4 = *(const float4*)&uS[((a0 + a) * 8 + hj) * 268 + d];
                ot[a] = fmaf(u4.x, w0, fmaf(u4.y, w1, fmaf(u4.z, w2, fmaf(u4.w, w3, ot[a]))));
            }
        }
        __syncthreads();
        #pragma unroll
        for (int a = 0; a < 4; a++) oS[(a0 + a) * 268 + j2] = ot[a];
    }
    __syncthreads();

    // ---- x = x_anc + oS @ Wo via mma ----
    {
        float acc[2][4] = {{0.f,0.f,0.f,0.f},{0.f,0.f,0.f,0.f}};
        for (int ks = 0; ks < 32; ks++) {
            const int kb = ks * 8;
            float q0 = oS[lg * 268 + kb + lc];
            float q1 = oS[lg * 268 + kb + lc + 4];
            uint32_t ahi[4], alo[4];
            ahi[0] = f2tf(q0); alo[0] = f2tf(q0 - __uint_as_float(ahi[0]));
            ahi[2] = f2tf(q1); alo[2] = f2tf(q1 - __uint_as_float(ahi[2]));
            ahi[1] = alo[1] = ahi[3] = alo[3] = 0u;
            #pragma unroll
            for (int nt = 0; nt < 2; nt++) {
                uint4 v = g_wof[(ks * 32 + wid * 2 + nt) * 32 + lane];
                uint32_t bhi[2] = {v.x, v.z}, blo[2] = {v.y, v.w};
                mma8(acc[nt], alo, bhi);
                mma8(acc[nt], ahi, blo);
                mma8(acc[nt], ahi, bhi);
            }
        }
        #pragma unroll
        for (int nt = 0; nt < 2; nt++) {
            const int col = wid * 16 + nt * 8 + lc * 2;
            const size_t idx = (size_t)(b0 + lg) * Dn + col;
            g_x[idx]     = x_anc[idx]     + acc[nt][0];
            g_x[idx + 1] = x_anc[idx + 1] + acc[nt][1];
        }
    }
}

// ---------------------------------------------------------------------------
// FFN (unchanged): LN2 -> ff1(mma)+gelu -> ff2(mma)+residual.
// ---------------------------------------------------------------------------
__global__ __launch_bounds__(512, 1) void ffn_mma3(
    const float* __restrict__ ln2g, const float* __restrict__ ln2b,
    const float* __restrict__ ff1b, const float* __restrict__ ff2b,
    float* __restrict__ out)
{
    extern __shared__ uint2 su[];
    uint2* hHL   = su;
    uint2* actHL = su + 32 * FH_STRIDE;

    const int tid = threadIdx.x, wid = tid >> 5, lane = tid & 31;
    const int lg = lane >> 2, lc = lane & 3;
    const int row0 = blockIdx.x * 32;

    #pragma unroll
    for (int rr = 0; rr < 2; rr++) {
        const int row = wid * 2 + rr;
        const float* xr = g_x + (size_t)(row0 + row) * Dn;
        float4 v0 = *(const float4*)&xr[lane * 8];
        float4 v1 = *(const float4*)&xr[lane * 8 + 4];
        float v[8] = {v0.x, v0.y, v0.z, v0.w, v1.x, v1.y, v1.z, v1.w};
        float s = 0.f, s2 = 0.f;
        #pragma unroll
        for (int t = 0; t < 8; t++) { s += v[t]; s2 += v[t] * v[t]; }
        #pragma unroll
        for (int o = 16; o; o >>= 1) {
            s  += __shfl_xor_sync(0xffffffffu, s,  o);
            s2 += __shfl_xor_sync(0xffffffffu, s2, o);
        }
        const float mu   = s * (1.0f / Dn);
        const float var  = s2 * (1.0f / Dn) - mu * mu;
        const float rstd = rsqrtf(var + 1e-5f);
        #pragma unroll
        for (int t = 0; t < 8; t++) {
            const int c = lane * 8 + t;
            float hv = (v[t] - mu) * rstd * ln2g[c] + ln2b[c];
            uint32_t hi = f2tf(hv);
            hHL[row * FH_STRIDE + c] = make_uint2(hi, f2tf(hv - __uint_as_float(hi)));
        }
    }
    __syncthreads();

    float acc2[2][2][4];
    #pragma unroll
    for (int mt = 0; mt < 2; mt++)
        #pragma unroll
        for (int nt = 0; nt < 2; nt++)
            #pragma unroll
            for (int e = 0; e < 4; e++) acc2[mt][nt][e] = 0.f;

    for (int half = 0; half < 2; half++) {
        float acc[2][4][4];
        #pragma unroll
        for (int mt = 0; mt < 2; mt++)
            #pragma unroll
            for (int nt = 0; nt < 4; nt++)
                #pragma unroll
                for (int e = 0; e < 4; e++) acc[mt][nt][e] = 0.f;

        for (int ks = 0; ks < 32; ks++) {
            const int kb = ks * 8;
            uint32_t ahi[2][4], alo[2][4];
            #pragma unroll
            for (int mt = 0; mt < 2; mt++) {
                const int r0 = mt * 16 + lg;
                uint2 p0 = hHL[r0 * FH_STRIDE + kb + lc];
                uint2 p1 = hHL[(r0 + 8) * FH_STRIDE + kb + lc];
                uint2 p2 = hHL[r0 * FH_STRIDE + kb + lc + 4];
                uint2 p3 = hHL[(r0 + 8) * FH_STRIDE + kb + lc + 4];
                ahi[mt][0] = p0.x; alo[mt][0] = p0.y;
                ahi[mt][1] = p1.x; alo[mt][1] = p1.y;
                ahi[mt][2] = p2.x; alo[mt][2] = p2.y;
                ahi[mt][3] = p3.x; alo[mt][3] = p3.y;
            }
            #pragma unroll
            for (int nt = 0; nt < 4; nt++) {
                const int ntile = half * 64 + wid * 4 + nt;
                uint4 v = g_w1f[(ks * 128 + ntile) * 32 + lane];
                uint32_t bhi[2] = {v.x, v.z}, blo[2] = {v.y, v.w};
                #pragma unroll
                for (int mt = 0; mt < 2; mt++) {
                    mma8(acc[mt][nt], alo[mt], bhi);
                    mma8(acc[mt][nt], ahi[mt], blo);
                    mma8(acc[mt][nt], ahi[mt], bhi);
                }
            }
        }

        #pragma unroll
        for (int mt = 0; mt < 2; mt++) {
            const int r0 = mt * 16 + lg;
            #pragma unroll
            for (int nt = 0; nt < 4; nt++) {
                const int lcol = wid * 32 + nt * 8 + lc * 2;
                const int gcol = half * 512 + lcol;
                #pragma unroll
                for (int e = 0; e < 2; e++) {
                    const float bb = ff1b[gcol + e];
                    float u0 = acc[mt][nt][e] + bb;
                    float u1 = acc[mt][nt][2 + e] + bb;
                    float g0 = 0.5f * u0 * (1.0f + erff(u0 * 0.70710678118654752f));
                    float g1v = 0.5f * u1 * (1.0f + erff(u1 * 0.70710678118654752f));
                    uint32_t h0 = f2tf(g0), h1 = f2tf(g1v);
                    actHL[r0 * FA_STRIDE + lcol + e] =
                        make_uint2(h0, f2tf(g0 - __uint_as_float(h0)));
                    actHL[(r0 + 8) * FA_STRIDE + lcol + e] =
                        make_uint2(h1, f2tf(g1v - __uint_as_float(h1)));
                }
            }
        }
        __syncthreads();

        for (int ks = 0; ks < 64; ks++) {
            const int kb = ks * 8;
            uint32_t ahi[2][4], alo[2][4];
            #pragma unroll
            for (int mt = 0; mt < 2; mt++) {
                const int r0 = mt * 16 + lg;
                uint2 p0 = actHL[r0 * FA_STRIDE + kb + lc];
                uint2 p1 = actHL[(r0 + 8) * FA_STRIDE + kb + lc];
                uint2 p2 = actHL[r0 * FA_STRIDE + kb + lc + 4];
                uint2 p3 = actHL[(r0 + 8) * FA_STRIDE + kb + lc + 4];
                ahi[mt][0] = p0.x; alo[mt][0] = p0.y;
                ahi[mt][1] = p1.x; alo[mt][1] = p1.y;
                ahi[mt][2] = p2.x; alo[mt][2] = p2.y;
                ahi[mt][3] = p3.x; alo[mt][3] = p3.y;
            }
            #pragma unroll
            for (int nt = 0; nt < 2; nt++) {
                const int ntile = wid * 2 + nt;
                const int ksg = half * 64 + ks;
                uint4 v = g_w2f[(ksg * 32 + ntile) * 32 + lane];
                uint32_t bhi[2] = {v.x, v.z}, blo[2] = {v.y, v.w};
                #pragma unroll
                for (int mt = 0; mt < 2; mt++) {
                    mma8(acc2[mt][nt], alo[mt], bhi);
                    mma8(acc2[mt][nt], ahi[mt], blo);
                    mma8(acc2[mt][nt], ahi[mt], bhi);
                }
            }
        }
        __syncthreads();
    }

    #pragma unroll
    for (int mt = 0; mt < 2; mt++) {
        const int r0 = mt * 16 + lg;
        #pragma unroll
        for (int nt = 0; nt < 2; nt++) {
            const int col = wid * 16 + nt * 8 + lc * 2;
            const float b0 = ff2b[col], b1 = ff2b[col + 1];
            const size_t i0 = (size_t)(row0 + r0) * Dn + col;
            const size_t i1 = (size_t)(row0 + r0 + 8) * Dn + col;
            out[i0]     = g_x[i0]     + acc2[mt][nt][0] + b0;
            out[i0 + 1] = g_x[i0 + 1] + acc2[mt][nt][1] + b1;
            out[i1]     = g_x[i1]     + acc2[mt][nt][2] + b0;
            out[i1 + 1] = g_x[i1 + 1] + acc2[mt][nt][3] + b1;
        }
    }
}

extern "C" void kernel_launch(void* const* d_in, const int* in_sizes, int n_in,
                              void* d_out, int out_size)
{
    const float* x_anc = (const float*)d_in[0];
    const float* x_nei = (const float*)d_in[1];
    const float* Wq    = (const float*)d_in[2];
    const float* Wk    = (const float*)d_in[3];
    const float* Wv    = (const float*)d_in[4];
    const float* Wo    = (const float*)d_in[5];
    const float* ln1g  = (const float*)d_in[6];
    const float* ln1b  = (const float*)d_in[7];
    const float* ln2g  = (const float*)d_in[8];
    const float* ln2b  = (const float*)d_in[9];
    const float* ff1w  = (const float*)d_in[10];
    const float* ff1b  = (const float*)d_in[11];
    const float* ff2w  = (const float*)d_in[12];
    const float* ff2b  = (const float*)d_in[13];
    float* out = (float*)d_out;

    static bool attr_set = false;
    if (!attr_set) {
        cudaFuncSetAttribute(attn7,    cudaFuncAttributeMaxDynamicSharedMemorySize, ATTN_SMEM);
        cudaFuncSetAttribute(ffn_mma3, cudaFuncAttributeMaxDynamicSharedMemorySize, FFN_SMEM);
        attr_set = true;
    }

    split_all<<<1408, 256>>>(Wq, Wk, Wo, ff1w, ff2w);
    attn7<<<Bn / 8, 512, ATTN_SMEM>>>(x_anc, x_nei, Wv, ln1g, ln1b);
    ffn_mma3<<<Bn / 32, 512, FFN_SMEM>>>(ln2g, ln2b, ff1b, ff2b, out);
}